// round 2
// baseline (speedup 1.0000x reference)
#include <cuda_runtime.h>
#include <cstdint>

// ---------------- static scratch (no allocs allowed) ----------------
#define NMAX 100352
#define EMAX 1700000

__device__ int   g_deg[NMAX];
__device__ int   g_off[NMAX + 1];
__device__ int   g_cur[NMAX];
__device__ int   g_csr[EMAX];
__device__ float g_cnt[NMAX];
__device__ float g_bufA[(size_t)NMAX * 256];
__device__ float g_bufB[(size_t)NMAX * 256];
__device__ float g_meanb[(size_t)NMAX * 256];

// ---------------- CSR build ----------------
__global__ void k_zero(int n) {
    int i = blockIdx.x * blockDim.x + threadIdx.x;
    if (i < n) g_deg[i] = 0;
}

__global__ void k_hist(const int* __restrict__ dst, int E) {
    int e = blockIdx.x * blockDim.x + threadIdx.x;
    if (e < E) atomicAdd(&g_deg[dst[e]], 1);
}

// single block, 1024 threads: exclusive scan of deg -> off, also cur, cnt
__global__ void k_scan(int n) {
    __shared__ int part[1024];
    int t = threadIdx.x;
    int chunk = (n + 1023) / 1024;
    int beg = t * chunk;
    int end = min(beg + chunk, n);
    int s = 0;
    for (int i = beg; i < end; i++) s += g_deg[i];
    part[t] = s;
    __syncthreads();
    // inclusive Hillis-Steele scan
    for (int off = 1; off < 1024; off <<= 1) {
        int v = (t >= off) ? part[t - off] : 0;
        __syncthreads();
        part[t] += v;
        __syncthreads();
    }
    int run = (t == 0) ? 0 : part[t - 1];
    for (int i = beg; i < end; i++) {
        int d = g_deg[i];
        g_off[i] = run;
        g_cur[i] = run;
        g_cnt[i] = (d > 0) ? (float)d : 1.0f;
        run += d;
    }
    if (end == n) g_off[n] = run;
}

__global__ void k_scatter(const int* __restrict__ src, const int* __restrict__ dst, int E) {
    int e = blockIdx.x * blockDim.x + threadIdx.x;
    if (e < E) {
        int p = atomicAdd(&g_cur[dst[e]], 1);
        g_csr[p] = src[e];
    }
}

// canonicalize segment order (determinism across replays): insertion sort per node
__global__ void k_sortseg(int n) {
    int i = blockIdx.x * blockDim.x + threadIdx.x;
    if (i >= n) return;
    int b = g_off[i], e = g_off[i + 1];
    for (int j = b + 1; j < e; j++) {
        int v = g_csr[j];
        int k = j - 1;
        while (k >= b && g_csr[k] > v) { g_csr[k + 1] = g_csr[k]; k--; }
        g_csr[k + 1] = v;
    }
}

// ---------------- mean aggregation: one warp per node ----------------
template <int D>
__global__ void k_agg(const float* __restrict__ x, float* __restrict__ meanp, int n) {
    int gw = (blockIdx.x * blockDim.x + threadIdx.x) >> 5;
    int lane = threadIdx.x & 31;
    if (gw >= n) return;
    int b = g_off[gw], e = g_off[gw + 1];
    constexpr int IT = D / 128;
    float4 acc[IT];
#pragma unroll
    for (int it = 0; it < IT; it++) acc[it] = make_float4(0.f, 0.f, 0.f, 0.f);
    for (int j = b; j < e; j++) {
        const float4* row = (const float4*)(x + (size_t)g_csr[j] * D);
#pragma unroll
        for (int it = 0; it < IT; it++) {
            float4 v = row[lane + it * 32];
            acc[it].x += v.x; acc[it].y += v.y; acc[it].z += v.z; acc[it].w += v.w;
        }
    }
    float inv = 1.0f / g_cnt[gw];
    float4* mo = (float4*)(meanp + (size_t)gw * D);
#pragma unroll
    for (int it = 0; it < IT; it++) {
        float4 v = acc[it];
        v.x *= inv; v.y *= inv; v.z *= inv; v.w *= inv;
        mo[lane + it * 32] = v;
    }
}

// ---------------- fused dual-GEMM + bias + LayerNorm + ReLU ----------------
// C[n, DOUT] = LNReLU( mean @ W0 + x @ W1 + b )
// Block: 256 threads, tile 64 rows x DOUT cols. Warp w owns rows w*8..w*8+7
// entirely (8 rows x TN cols-per-lane), enabling warp-shuffle LayerNorm.
template <int DIN, int DOUT>
__launch_bounds__(256)
__global__ void k_gemm_ln(const float* __restrict__ A0, const float* __restrict__ A1,
                          const float* __restrict__ W0, const float* __restrict__ W1,
                          const float* __restrict__ bias, const float* __restrict__ gamma,
                          const float* __restrict__ beta, float* __restrict__ out, int n) {
    constexpr int TN = DOUT / 32;
    __shared__ float As[64][16];
    __shared__ float Ws[16][DOUT];

    int t = threadIdx.x;
    int lane = t & 31;
    int warp = t >> 5;
    int row0 = blockIdx.x * 64;

    float acc[8][TN];
#pragma unroll
    for (int m = 0; m < 8; m++)
#pragma unroll
        for (int j = 0; j < TN; j++) acc[m][j] = 0.f;

    for (int ph = 0; ph < 2; ph++) {
        const float* A = ph ? A1 : A0;
        const float* W = ph ? W1 : W0;
        for (int k0 = 0; k0 < DIN; k0 += 16) {
            __syncthreads();
            {   // A tile: 64x16, one float4 per thread
                int ar = t >> 2;
                int ac = (t & 3) * 4;
                int gr = row0 + ar;
                float4 v = make_float4(0.f, 0.f, 0.f, 0.f);
                if (gr < n) v = *(const float4*)(A + (size_t)gr * DIN + k0 + ac);
                *(float4*)&As[ar][ac] = v;
            }
            {   // W tile: 16 x DOUT
                constexpr int NC4 = DOUT / 4;
#pragma unroll
                for (int i = 0; i < 16 * NC4 / 256; i++) {
                    int idx = t + i * 256;
                    int wrw = idx / NC4;
                    int wc = (idx % NC4) * 4;
                    *(float4*)&Ws[wrw][wc] = *(const float4*)(W + (size_t)(k0 + wrw) * DOUT + wc);
                }
            }
            __syncthreads();
#pragma unroll
            for (int kk = 0; kk < 16; kk++) {
                float a[8];
#pragma unroll
                for (int m = 0; m < 8; m++) a[m] = As[warp * 8 + m][kk];
                float wv[TN];
#pragma unroll
                for (int j = 0; j < TN; j++) wv[j] = Ws[kk][lane + 32 * j];
#pragma unroll
                for (int m = 0; m < 8; m++)
#pragma unroll
                    for (int j = 0; j < TN; j++) acc[m][j] = fmaf(a[m], wv[j], acc[m][j]);
            }
        }
    }

    // epilogue: +bias, LayerNorm over DOUT (warp shuffles), scale/shift, ReLU
    float bia[TN], ga[TN], bt[TN];
#pragma unroll
    for (int j = 0; j < TN; j++) {
        int c = lane + 32 * j;
        bia[j] = bias[c];
        ga[j] = gamma[c];
        bt[j] = beta[c];
    }
#pragma unroll
    for (int m = 0; m < 8; m++) {
        int row = row0 + warp * 8 + m;
        float v[TN];
        float s = 0.f, ss = 0.f;
#pragma unroll
        for (int j = 0; j < TN; j++) {
            v[j] = acc[m][j] + bia[j];
            s += v[j];
            ss += v[j] * v[j];
        }
#pragma unroll
        for (int o = 16; o; o >>= 1) {
            s += __shfl_xor_sync(0xffffffffu, s, o);
            ss += __shfl_xor_sync(0xffffffffu, ss, o);
        }
        float mu = s * (1.0f / DOUT);
        float var = ss * (1.0f / DOUT) - mu * mu;
        float rs = rsqrtf(var + 1e-5f);
        if (row < n) {
#pragma unroll
            for (int j = 0; j < TN; j++) {
                float ov = fmaxf((v[j] - mu) * rs * ga[j] + bt[j], 0.f);
                out[(size_t)row * DOUT + lane + 32 * j] = ov;
            }
        }
    }
}

// ---------------- final layer: DIN=128 -> DOUT=9, no LN ----------------
__global__ void k_out(const float* __restrict__ meanp, const float* __restrict__ x,
                      const float* __restrict__ wm, const float* __restrict__ wr,
                      const float* __restrict__ bias, float* __restrict__ out, int n) {
    __shared__ float swm[128 * 9];
    __shared__ float swr[128 * 9];
    __shared__ float sb[9];
    for (int i = threadIdx.x; i < 128 * 9; i += blockDim.x) {
        swm[i] = wm[i];
        swr[i] = wr[i];
    }
    if (threadIdx.x < 9) sb[threadIdx.x] = bias[threadIdx.x];
    __syncthreads();

    int gw = (blockIdx.x * blockDim.x + threadIdx.x) >> 5;
    int lane = threadIdx.x & 31;
    if (gw >= n) return;

    float4 am = ((const float4*)(meanp + (size_t)gw * 128))[lane];
    float4 ax = ((const float4*)(x + (size_t)gw * 128))[lane];
    float a4[4] = {am.x, am.y, am.z, am.w};
    float x4[4] = {ax.x, ax.y, ax.z, ax.w};

    float o[9];
#pragma unroll
    for (int j = 0; j < 9; j++) o[j] = 0.f;
#pragma unroll
    for (int q = 0; q < 4; q++) {
        int k = lane * 4 + q;
#pragma unroll
        for (int j = 0; j < 9; j++)
            o[j] += a4[q] * swm[k * 9 + j] + x4[q] * swr[k * 9 + j];
    }
#pragma unroll
    for (int j = 0; j < 9; j++)
#pragma unroll
        for (int s = 16; s; s >>= 1) o[j] += __shfl_xor_sync(0xffffffffu, o[j], s);
    if (lane < 9) out[(size_t)gw * 9 + lane] = o[lane] + sb[lane];
}

// ---------------- launch ----------------
extern "C" void kernel_launch(void* const* d_in, const int* in_sizes, int n_in,
                              void* d_out, int out_size) {
    const float* z = (const float*)d_in[0];
    const int* ei = (const int*)d_in[1];
    const float* wm1 = (const float*)d_in[2];
    const float* wr1 = (const float*)d_in[3];
    const float* b1 = (const float*)d_in[4];
    const float* g1 = (const float*)d_in[5];
    const float* be1 = (const float*)d_in[6];
    const float* wm2 = (const float*)d_in[7];
    const float* wr2 = (const float*)d_in[8];
    const float* b2 = (const float*)d_in[9];
    const float* g2 = (const float*)d_in[10];
    const float* be2 = (const float*)d_in[11];
    const float* wm3 = (const float*)d_in[12];
    const float* wr3 = (const float*)d_in[13];
    const float* b3 = (const float*)d_in[14];
    const float* g3 = (const float*)d_in[15];
    const float* be3 = (const float*)d_in[16];
    const float* wm4 = (const float*)d_in[17];
    const float* wr4 = (const float*)d_in[18];
    const float* b4 = (const float*)d_in[19];

    int N = in_sizes[0] / 128;
    int E = in_sizes[1] / 2;
    const int* src = ei;
    const int* dst = ei + E;

    float *bufA, *bufB, *meanb;
    void* p;
    cudaGetSymbolAddress(&p, g_bufA);  bufA = (float*)p;
    cudaGetSymbolAddress(&p, g_bufB);  bufB = (float*)p;
    cudaGetSymbolAddress(&p, g_meanb); meanb = (float*)p;

    // CSR build (deterministic after segment sort)
    k_zero<<<(N + 255) / 256, 256>>>(N);
    k_hist<<<(E + 255) / 256, 256>>>(dst, E);
    k_scan<<<1, 1024>>>(N);
    k_scatter<<<(E + 255) / 256, 256>>>(src, dst, E);
    k_sortseg<<<(N + 255) / 256, 256>>>(N);

    int aggBlocks = (N + 7) / 8;       // warp per node, 256 thr/block
    int gemmBlocks = (N + 63) / 64;

    // Layer 1: 128 -> 256
    k_agg<128><<<aggBlocks, 256>>>(z, meanb, N);
    k_gemm_ln<128, 256><<<gemmBlocks, 256>>>(meanb, z, wm1, wr1, b1, g1, be1, bufA, N);
    // Layer 2: 256 -> 256
    k_agg<256><<<aggBlocks, 256>>>(bufA, meanb, N);
    k_gemm_ln<256, 256><<<gemmBlocks, 256>>>(meanb, bufA, wm2, wr2, b2, g2, be2, bufB, N);
    // Layer 3: 256 -> 128
    k_agg<256><<<aggBlocks, 256>>>(bufB, meanb, N);
    k_gemm_ln<256, 128><<<gemmBlocks, 256>>>(meanb, bufB, wm3, wr3, b3, g3, be3, bufA, N);
    // Layer 4: 128 -> 9 (no LN)
    k_agg<128><<<aggBlocks, 256>>>(bufA, meanb, N);
    k_out<<<aggBlocks, 256>>>(meanb, bufA, wm4, wr4, b4, (float*)d_out, N);
}

// round 5
// speedup vs baseline: 1.6342x; 1.6342x over previous
#include <cuda_runtime.h>
#include <cstdint>

// ================= static scratch =================
#define NMAX 100352
#define EMAX 1700000

__device__ int   g_deg[NMAX];
__device__ int   g_off[NMAX + 1];
__device__ int   g_cur[NMAX];
__device__ int   g_csr[EMAX];
__device__ float g_cnt[NMAX];
__device__ float g_bufA[(size_t)NMAX * 256];
__device__ float g_bufB[(size_t)NMAX * 256];
__device__ float g_meanb[(size_t)NMAX * 256];

// ================= helpers =================
__device__ __forceinline__ uint32_t tf32r(float f) {
    uint32_t u;
    asm("cvt.rna.tf32.f32 %0, %1;" : "=r"(u) : "f"(f));
    return u;
}
__device__ __forceinline__ void mma_tf32(float* c, uint32_t a0, uint32_t a1, uint32_t a2, uint32_t a3,
                                         uint32_t b0, uint32_t b1) {
    asm volatile("mma.sync.aligned.m16n8k8.row.col.f32.tf32.tf32.f32 "
                 "{%0,%1,%2,%3}, {%4,%5,%6,%7}, {%8,%9}, {%0,%1,%2,%3};"
                 : "+f"(c[0]), "+f"(c[1]), "+f"(c[2]), "+f"(c[3])
                 : "r"(a0), "r"(a1), "r"(a2), "r"(a3), "r"(b0), "r"(b1));
}

// ================= CSR build =================
__global__ void k_zero(int n) {
    int i = blockIdx.x * blockDim.x + threadIdx.x;
    if (i < n) g_deg[i] = 0;
}
__global__ void k_hist(const int* __restrict__ dst, int E) {
    int e = blockIdx.x * blockDim.x + threadIdx.x;
    if (e < E) atomicAdd(&g_deg[dst[e]], 1);
}
__global__ void k_scan(int n) {
    __shared__ int part[1024];
    int t = threadIdx.x;
    int chunk = (n + 1023) / 1024;
    int beg = t * chunk;
    int end = min(beg + chunk, n);
    int s = 0;
    for (int i = beg; i < end; i++) s += g_deg[i];
    part[t] = s;
    __syncthreads();
    for (int off = 1; off < 1024; off <<= 1) {
        int v = (t >= off) ? part[t - off] : 0;
        __syncthreads();
        part[t] += v;
        __syncthreads();
    }
    int run = (t == 0) ? 0 : part[t - 1];
    for (int i = beg; i < end; i++) {
        int d = g_deg[i];
        g_off[i] = run;
        g_cur[i] = run;
        g_cnt[i] = (d > 0) ? (float)d : 1.0f;
        run += d;
    }
    if (end == n) g_off[n] = run;
}
__global__ void k_scatter(const int* __restrict__ src, const int* __restrict__ dst, int E) {
    int e = blockIdx.x * blockDim.x + threadIdx.x;
    if (e < E) {
        int p = atomicAdd(&g_cur[dst[e]], 1);
        g_csr[p] = src[e];
    }
}
__global__ void k_sortseg(int n) {
    int i = blockIdx.x * blockDim.x + threadIdx.x;
    if (i >= n) return;
    int b = g_off[i], e = g_off[i + 1];
    for (int j = b + 1; j < e; j++) {
        int v = g_csr[j];
        int k = j - 1;
        while (k >= b && g_csr[k] > v) { g_csr[k + 1] = g_csr[k]; k--; }
        g_csr[k + 1] = v;
    }
}

// ================= mean aggregation: one warp per node =================
template <int D>
__global__ void k_agg(const float* __restrict__ x, float* __restrict__ meanp, int n) {
    int gw = (blockIdx.x * blockDim.x + threadIdx.x) >> 5;
    int lane = threadIdx.x & 31;
    if (gw >= n) return;
    int b = g_off[gw], e = g_off[gw + 1];
    constexpr int IT = D / 128;
    float4 acc[IT];
#pragma unroll
    for (int it = 0; it < IT; it++) acc[it] = make_float4(0.f, 0.f, 0.f, 0.f);
    for (int j = b; j < e; j++) {
        const float4* row = (const float4*)(x + (size_t)g_csr[j] * D);
#pragma unroll
        for (int it = 0; it < IT; it++) {
            float4 v = row[lane + it * 32];
            acc[it].x += v.x; acc[it].y += v.y; acc[it].z += v.z; acc[it].w += v.w;
        }
    }
    float inv = 1.0f / g_cnt[gw];
    float4* mo = (float4*)(meanp + (size_t)gw * D);
#pragma unroll
    for (int it = 0; it < IT; it++) {
        float4 v = acc[it];
        v.x *= inv; v.y *= inv; v.z *= inv; v.w *= inv;
        mo[lane + it * 32] = v;
    }
}

// ================= tf32 mma.sync fused dual-GEMM + bias + LN + ReLU =================
// out[128 x DOUT] = LNReLU( A0 @ W0 + A1 @ W1 + b ), W as [DIN][DOUT] row-major.
// 512 threads = 16 warps: warp = (mw = w&7: rows mw*16..+15) x (nh = w>>3: cols nh*DOUT/2..).
// Fragment pairing per PTX m16n8k8 tf32: k-pairs are (tq, tq+4).
// A fragments stored k-paired with XOR-by-ks swizzle (conflict-free STS + LDS.64).
template <int DIN, int DOUT>
__launch_bounds__(512, 1)
__global__ void k_gemm_tc(const float* __restrict__ A0, const float* __restrict__ A1,
                          const float* __restrict__ W0, const float* __restrict__ W1,
                          const float* __restrict__ bias, const float* __restrict__ gamma,
                          const float* __restrict__ beta, float* __restrict__ out, int n) {
    extern __shared__ float sm[];
    constexpr int NCH = DIN / 32;          // k-chunks per phase
    constexpr int TOT = 2 * NCH;
    constexpr int NP = DOUT / 128;         // B staging passes
    constexpr int BNh = DOUT / 2;
    constexpr int NT = BNh / 8;            // n-tiles per warp
    constexpr int ASZ = 128 * 32;          // floats per A buffer
    constexpr int BSZ = DOUT * 32;         // floats per B buffer

    float* Abuf[2] = { sm, sm + ASZ };
    float* Bbuf[2] = { sm + 2 * ASZ, sm + 2 * ASZ + BSZ };
    float* sp = sm + 2 * ASZ + 2 * BSZ;    // bias | gamma | beta
    float* sln = sp + 3 * DOUT;            // [128][2] float2 (s, ss)

    int t = threadIdx.x;
    int wid = t >> 5, lane = t & 31;
    int g = lane >> 2, tq = lane & 3;
    int mw = wid & 7, nh = wid >> 3;
    int nbase = nh * BNh;
    int row0 = blockIdx.x * 128;

    for (int i = t; i < DOUT; i += 512) {
        sp[i] = bias[i];
        sp[DOUT + i] = gamma[i];
        sp[2 * DOUT + i] = beta[i];
    }

    float acc[NT][4];
#pragma unroll
    for (int nt = 0; nt < NT; nt++)
#pragma unroll
        for (int j = 0; j < 4; j++) acc[nt][j] = 0.f;

    // staging thread roles
    int sa_r[2], sa_k4[2];
#pragma unroll
    for (int i = 0; i < 2; i++) {
        int idx = t + i * 512;
        sa_r[i] = idx >> 3;
        sa_k4[i] = idx & 7;
    }
    int sb_kp = t & 3;
    int sb_n = t >> 2;

    float4 av[2];
    float bv0[4 * NP], bv1[4 * NP];

    // ---- LDG for chunk c ----
    auto ldg_chunk = [&](int c) {
        const float* A = (c < NCH) ? A0 : A1;
        const float* W = (c < NCH) ? W0 : W1;
        int k0 = ((c < NCH) ? c : c - NCH) * 32;
#pragma unroll
        for (int i = 0; i < 2; i++) {
            int gr = row0 + sa_r[i];
            float4 v = make_float4(0.f, 0.f, 0.f, 0.f);
            if (gr < n) v = *(const float4*)(A + (size_t)gr * DIN + k0 + sa_k4[i] * 4);
            av[i] = v;
        }
#pragma unroll
        for (int ks = 0; ks < 4; ks++)
#pragma unroll
            for (int np = 0; np < NP; np++) {
                int k = k0 + ks * 8 + sb_kp;        // pair (k, k+4)
                int nn = sb_n + np * 128;
                bv0[ks * NP + np] = W[(size_t)k * DOUT + nn];
                bv1[ks * NP + np] = W[(size_t)(k + 4) * DOUT + nn];
            }
    };

    // ---- STS into buffer b ----
    // A pair layout: float offset (ks*128 + m)*8 + ((kk ^ ks)*2 + e),
    //   pair kk holds (A[m][ks*8+kk], A[m][ks*8+kk+4]); e = which element.
    auto sts_chunk = [&](int b) {
        float* Af = Abuf[b];
#pragma unroll
        for (int i = 0; i < 2; i++) {
            int q = sa_k4[i] >> 1, e = sa_k4[i] & 1;  // thread's float4 = local k e*4..e*4+3 of group q
            int base = (q * 128 + sa_r[i]) * 8;
            float vals[4] = { av[i].x, av[i].y, av[i].z, av[i].w };
#pragma unroll
            for (int cc = 0; cc < 4; cc++)
                Af[base + ((cc ^ q) * 2 + e)] = __uint_as_float(tf32r(vals[cc]));
        }
        float2* Bu = (float2*)Bbuf[b];
#pragma unroll
        for (int ks = 0; ks < 4; ks++)
#pragma unroll
            for (int np = 0; np < NP; np++) {
                int nn = sb_n + np * 128;
                float2 p;
                p.x = __uint_as_float(tf32r(bv0[ks * NP + np]));
                p.y = __uint_as_float(tf32r(bv1[ks * NP + np]));
                Bu[(ks * DOUT + nn) * 4 + sb_kp] = p;
            }
    };

    // ---- MMA on buffer b ----
    auto mma_chunk = [&](int b) {
        const uint2* Au = (const uint2*)Abuf[b];
        const uint2* Bu = (const uint2*)Bbuf[b];
        int arow = mw * 16 + g;
#pragma unroll
        for (int ks = 0; ks < 4; ks++) {
            int kk = tq ^ ks;  // undo store swizzle
            uint2 aA = Au[(ks * 128 + arow) * 4 + kk];       // (A[row][tq],   A[row][tq+4])
            uint2 aB = Au[(ks * 128 + arow + 8) * 4 + kk];   // (A[row+8][tq], A[row+8][tq+4])
#pragma unroll
            for (int nt = 0; nt < NT; nt++) {
                uint2 bb = Bu[(ks * DOUT + nbase + nt * 8 + g) * 4 + tq];  // (B[tq][n], B[tq+4][n])
                mma_tf32(acc[nt], aA.x, aB.x, aA.y, aB.y, bb.x, bb.y);
            }
        }
    };

    ldg_chunk(0);
    sts_chunk(0);
    __syncthreads();
    for (int c = 0; c < TOT; c++) {
        if (c + 1 < TOT) ldg_chunk(c + 1);
        mma_chunk(c & 1);
        if (c + 1 < TOT) sts_chunk((c + 1) & 1);
        __syncthreads();
    }

    // ---- epilogue: +bias, LN over DOUT, scale/shift, ReLU ----
    float s0 = 0.f, ss0 = 0.f, s1 = 0.f, ss1 = 0.f;
#pragma unroll
    for (int nt = 0; nt < NT; nt++) {
        int col = nbase + nt * 8 + 2 * tq;
        float b0 = sp[col], b1 = sp[col + 1];
        acc[nt][0] += b0; acc[nt][1] += b1;
        acc[nt][2] += b0; acc[nt][3] += b1;
        s0 += acc[nt][0] + acc[nt][1];
        ss0 += acc[nt][0] * acc[nt][0] + acc[nt][1] * acc[nt][1];
        s1 += acc[nt][2] + acc[nt][3];
        ss1 += acc[nt][2] * acc[nt][2] + acc[nt][3] * acc[nt][3];
    }
#pragma unroll
    for (int o = 1; o <= 2; o <<= 1) {
        s0 += __shfl_xor_sync(0xffffffffu, s0, o);
        ss0 += __shfl_xor_sync(0xffffffffu, ss0, o);
        s1 += __shfl_xor_sync(0xffffffffu, s1, o);
        ss1 += __shfl_xor_sync(0xffffffffu, ss1, o);
    }
    int rl0 = mw * 16 + g, rl1 = rl0 + 8;
    if (tq == 0) {
        ((float2*)sln)[rl0 * 2 + nh] = make_float2(s0, ss0);
        ((float2*)sln)[rl1 * 2 + nh] = make_float2(s1, ss1);
    }
    __syncthreads();
    float2 p00 = ((float2*)sln)[rl0 * 2 + 0], p01 = ((float2*)sln)[rl0 * 2 + 1];
    float2 p10 = ((float2*)sln)[rl1 * 2 + 0], p11 = ((float2*)sln)[rl1 * 2 + 1];
    float mu0 = (p00.x + p01.x) * (1.0f / DOUT);
    float var0 = (p00.y + p01.y) * (1.0f / DOUT) - mu0 * mu0;
    float rs0 = rsqrtf(var0 + 1e-5f);
    float mu1 = (p10.x + p11.x) * (1.0f / DOUT);
    float var1 = (p10.y + p11.y) * (1.0f / DOUT) - mu1 * mu1;
    float rs1 = rsqrtf(var1 + 1e-5f);

    int grow0 = row0 + rl0, grow1 = row0 + rl1;
#pragma unroll
    for (int nt = 0; nt < NT; nt++) {
        int col = nbase + nt * 8 + 2 * tq;
        float ga0 = sp[DOUT + col], ga1 = sp[DOUT + col + 1];
        float bt0 = sp[2 * DOUT + col], bt1 = sp[2 * DOUT + col + 1];
        if (grow0 < n) {
            float2 v;
            v.x = fmaxf((acc[nt][0] - mu0) * rs0 * ga0 + bt0, 0.f);
            v.y = fmaxf((acc[nt][1] - mu0) * rs0 * ga1 + bt1, 0.f);
            *(float2*)(out + (size_t)grow0 * DOUT + col) = v;
        }
        if (grow1 < n) {
            float2 v;
            v.x = fmaxf((acc[nt][2] - mu1) * rs1 * ga0 + bt0, 0.f);
            v.y = fmaxf((acc[nt][3] - mu1) * rs1 * ga1 + bt1, 0.f);
            *(float2*)(out + (size_t)grow1 * DOUT + col) = v;
        }
    }
}

// ================= final layer: 128 -> 9 =================
__global__ void k_out(const float* __restrict__ meanp, const float* __restrict__ x,
                      const float* __restrict__ wm, const float* __restrict__ wr,
                      const float* __restrict__ bias, float* __restrict__ out, int n) {
    __shared__ float swm[128 * 9];
    __shared__ float swr[128 * 9];
    __shared__ float sb[9];
    for (int i = threadIdx.x; i < 128 * 9; i += blockDim.x) {
        swm[i] = wm[i];
        swr[i] = wr[i];
    }
    if (threadIdx.x < 9) sb[threadIdx.x] = bias[threadIdx.x];
    __syncthreads();

    int gw = (blockIdx.x * blockDim.x + threadIdx.x) >> 5;
    int lane = threadIdx.x & 31;
    if (gw >= n) return;

    float4 am = ((const float4*)(meanp + (size_t)gw * 128))[lane];
    float4 ax = ((const float4*)(x + (size_t)gw * 128))[lane];
    float a4[4] = {am.x, am.y, am.z, am.w};
    float x4[4] = {ax.x, ax.y, ax.z, ax.w};

    float o[9];
#pragma unroll
    for (int j = 0; j < 9; j++) o[j] = 0.f;
#pragma unroll
    for (int q = 0; q < 4; q++) {
        int k = lane * 4 + q;
#pragma unroll
        for (int j = 0; j < 9; j++)
            o[j] += a4[q] * swm[k * 9 + j] + x4[q] * swr[k * 9 + j];
    }
#pragma unroll
    for (int j = 0; j < 9; j++)
#pragma unroll
        for (int s = 16; s; s >>= 1) o[j] += __shfl_xor_sync(0xffffffffu, o[j], s);
    if (lane < 9) out[(size_t)gw * 9 + lane] = o[lane] + sb[lane];
}

// ================= launch =================
extern "C" void kernel_launch(void* const* d_in, const int* in_sizes, int n_in,
                              void* d_out, int out_size) {
    const float* z = (const float*)d_in[0];
    const int* ei = (const int*)d_in[1];
    const float* wm1 = (const float*)d_in[2];
    const float* wr1 = (const float*)d_in[3];
    const float* b1 = (const float*)d_in[4];
    const float* g1 = (const float*)d_in[5];
    const float* be1 = (const float*)d_in[6];
    const float* wm2 = (const float*)d_in[7];
    const float* wr2 = (const float*)d_in[8];
    const float* b2 = (const float*)d_in[9];
    const float* g2 = (const float*)d_in[10];
    const float* be2 = (const float*)d_in[11];
    const float* wm3 = (const float*)d_in[12];
    const float* wr3 = (const float*)d_in[13];
    const float* b3 = (const float*)d_in[14];
    const float* g3 = (const float*)d_in[15];
    const float* be3 = (const float*)d_in[16];
    const float* wm4 = (const float*)d_in[17];
    const float* wr4 = (const float*)d_in[18];
    const float* b4 = (const float*)d_in[19];

    int N = in_sizes[0] / 128;
    int E = in_sizes[1] / 2;
    const int* src = ei;
    const int* dst = ei + E;

    float *bufA, *bufB, *meanb;
    void* p;
    cudaGetSymbolAddress(&p, g_bufA);  bufA = (float*)p;
    cudaGetSymbolAddress(&p, g_bufB);  bufB = (float*)p;
    cudaGetSymbolAddress(&p, g_meanb); meanb = (float*)p;

    // dynamic smem: (2*4096 + 2*DOUT*32 + 3*DOUT + 512) floats
    const int SM256 = (8192 + 2 * 256 * 32 + 3 * 256 + 512) * 4;
    const int SM128 = (8192 + 2 * 128 * 32 + 3 * 128 + 512) * 4;
    cudaFuncSetAttribute(k_gemm_tc<128, 256>, cudaFuncAttributeMaxDynamicSharedMemorySize, SM256);
    cudaFuncSetAttribute(k_gemm_tc<256, 256>, cudaFuncAttributeMaxDynamicSharedMemorySize, SM256);
    cudaFuncSetAttribute(k_gemm_tc<256, 128>, cudaFuncAttributeMaxDynamicSharedMemorySize, SM128);

    // CSR build (deterministic after segment sort)
    k_zero<<<(N + 255) / 256, 256>>>(N);
    k_hist<<<(E + 255) / 256, 256>>>(dst, E);
    k_scan<<<1, 1024>>>(N);
    k_scatter<<<(E + 255) / 256, 256>>>(src, dst, E);
    k_sortseg<<<(N + 255) / 256, 256>>>(N);

    int aggBlocks = (N + 7) / 8;
    int gemmBlocks = (N + 127) / 128;

    // Layer 1: 128 -> 256
    k_agg<128><<<aggBlocks, 256>>>(z, meanb, N);
    k_gemm_tc<128, 256><<<gemmBlocks, 512, SM256>>>(meanb, z, wm1, wr1, b1, g1, be1, bufA, N);
    // Layer 2: 256 -> 256
    k_agg<256><<<aggBlocks, 256>>>(bufA, meanb, N);
    k_gemm_tc<256, 256><<<gemmBlocks, 512, SM256>>>(meanb, bufA, wm2, wr2, b2, g2, be2, bufB, N);
    // Layer 3: 256 -> 128
    k_agg<256><<<aggBlocks, 256>>>(bufB, meanb, N);
    k_gemm_tc<256, 128><<<gemmBlocks, 512, SM128>>>(meanb, bufB, wm3, wr3, b3, g3, be3, bufA, N);
    // Layer 4: 128 -> 9 (no LN)
    k_agg<128><<<aggBlocks, 256>>>(bufA, meanb, N);
    k_out<<<aggBlocks, 256>>>(meanb, bufA, wm4, wr4, b4, (float*)d_out, N);
}

// round 6
// speedup vs baseline: 1.7537x; 1.0731x over previous
#include <cuda_runtime.h>
#include <cstdint>

// ================= static scratch =================
#define NMAX 100352
#define EMAX 1700000

__device__ int   g_deg[NMAX];
__device__ int   g_off[NMAX + 1];
__device__ int   g_cur[NMAX];
__device__ int   g_csr[EMAX];
__device__ float g_cnt[NMAX];
__device__ float g_bufA[(size_t)NMAX * 256];
__device__ float g_bufB[(size_t)NMAX * 256];
__device__ float g_meanb[(size_t)NMAX * 256];
__device__ float g_ym9[(size_t)NMAX * 9];
__device__ float g_yr9[(size_t)NMAX * 9];

// ================= helpers =================
__device__ __forceinline__ uint32_t tf32r(float f) {
    uint32_t u;
    asm("cvt.rna.tf32.f32 %0, %1;" : "=r"(u) : "f"(f));
    return u;
}
__device__ __forceinline__ void mma_tf32(float* c, uint32_t a0, uint32_t a1, uint32_t a2, uint32_t a3,
                                         uint32_t b0, uint32_t b1) {
    asm volatile("mma.sync.aligned.m16n8k8.row.col.f32.tf32.tf32.f32 "
                 "{%0,%1,%2,%3}, {%4,%5,%6,%7}, {%8,%9}, {%0,%1,%2,%3};"
                 : "+f"(c[0]), "+f"(c[1]), "+f"(c[2]), "+f"(c[3])
                 : "r"(a0), "r"(a1), "r"(a2), "r"(a3), "r"(b0), "r"(b1));
}

// ================= CSR build =================
__global__ void k_zero(int n) {
    int i = blockIdx.x * blockDim.x + threadIdx.x;
    if (i < n) g_deg[i] = 0;
}
__global__ void k_hist(const int* __restrict__ dst, int E) {
    int e = blockIdx.x * blockDim.x + threadIdx.x;
    if (e < E) atomicAdd(&g_deg[dst[e]], 1);
}
__global__ void k_scan(int n) {
    __shared__ int part[1024];
    int t = threadIdx.x;
    int chunk = (n + 1023) / 1024;
    int beg = t * chunk;
    int end = min(beg + chunk, n);
    int s = 0;
    for (int i = beg; i < end; i++) s += g_deg[i];
    part[t] = s;
    __syncthreads();
    for (int off = 1; off < 1024; off <<= 1) {
        int v = (t >= off) ? part[t - off] : 0;
        __syncthreads();
        part[t] += v;
        __syncthreads();
    }
    int run = (t == 0) ? 0 : part[t - 1];
    for (int i = beg; i < end; i++) {
        int d = g_deg[i];
        g_off[i] = run;
        g_cur[i] = run;
        g_cnt[i] = (d > 0) ? (float)d : 1.0f;
        run += d;
    }
    if (end == n) g_off[n] = run;
}
__global__ void k_scatter(const int* __restrict__ src, const int* __restrict__ dst, int E) {
    int e = blockIdx.x * blockDim.x + threadIdx.x;
    if (e < E) {
        int p = atomicAdd(&g_cur[dst[e]], 1);
        g_csr[p] = src[e];
    }
}
__global__ void k_sortseg(int n) {
    int i = blockIdx.x * blockDim.x + threadIdx.x;
    if (i >= n) return;
    int b = g_off[i], e = g_off[i + 1];
    for (int j = b + 1; j < e; j++) {
        int v = g_csr[j];
        int k = j - 1;
        while (k >= b && g_csr[k] > v) { g_csr[k + 1] = g_csr[k]; k--; }
        g_csr[k + 1] = v;
    }
}

// ================= mean aggregation: one warp per node (2x edge unroll) =================
template <int D>
__global__ void k_agg(const float* __restrict__ x, float* __restrict__ meanp, int n) {
    int gw = (blockIdx.x * blockDim.x + threadIdx.x) >> 5;
    int lane = threadIdx.x & 31;
    if (gw >= n) return;
    int b = g_off[gw], e = g_off[gw + 1];
    constexpr int IT = D / 128;
    float4 acc[IT], acc2[IT];
#pragma unroll
    for (int it = 0; it < IT; it++) {
        acc[it] = make_float4(0.f, 0.f, 0.f, 0.f);
        acc2[it] = make_float4(0.f, 0.f, 0.f, 0.f);
    }
    int j = b;
    for (; j + 1 < e; j += 2) {
        const float4* r0 = (const float4*)(x + (size_t)g_csr[j] * D);
        const float4* r1 = (const float4*)(x + (size_t)g_csr[j + 1] * D);
#pragma unroll
        for (int it = 0; it < IT; it++) {
            float4 v0 = r0[lane + it * 32];
            float4 v1 = r1[lane + it * 32];
            acc[it].x += v0.x; acc[it].y += v0.y; acc[it].z += v0.z; acc[it].w += v0.w;
            acc2[it].x += v1.x; acc2[it].y += v1.y; acc2[it].z += v1.z; acc2[it].w += v1.w;
        }
    }
    if (j < e) {
        const float4* r0 = (const float4*)(x + (size_t)g_csr[j] * D);
#pragma unroll
        for (int it = 0; it < IT; it++) {
            float4 v0 = r0[lane + it * 32];
            acc[it].x += v0.x; acc[it].y += v0.y; acc[it].z += v0.z; acc[it].w += v0.w;
        }
    }
    float inv = 1.0f / g_cnt[gw];
    float4* mo = (float4*)(meanp + (size_t)gw * D);
#pragma unroll
    for (int it = 0; it < IT; it++) {
        float4 v = acc[it];
        v.x = (v.x + acc2[it].x) * inv;
        v.y = (v.y + acc2[it].y) * inv;
        v.z = (v.z + acc2[it].z) * inv;
        v.w = (v.w + acc2[it].w) * inv;
        mo[lane + it * 32] = v;
    }
}

// ================= tf32 mma.sync fused dual-GEMM + bias + LN + ReLU =================
// out[128 x DOUT] = LNReLU( A0 @ W0 + A1 @ W1 + b ), W as [DIN][DOUT] row-major.
template <int DIN, int DOUT>
__launch_bounds__(512, 1)
__global__ void k_gemm_tc(const float* __restrict__ A0, const float* __restrict__ A1,
                          const float* __restrict__ W0, const float* __restrict__ W1,
                          const float* __restrict__ bias, const float* __restrict__ gamma,
                          const float* __restrict__ beta, float* __restrict__ out, int n) {
    extern __shared__ float sm[];
    constexpr int NCH = DIN / 32;
    constexpr int TOT = 2 * NCH;
    constexpr int NP = DOUT / 128;
    constexpr int BNh = DOUT / 2;
    constexpr int NT = BNh / 8;
    constexpr int ASZ = 128 * 32;
    constexpr int BSZ = DOUT * 32;

    float* Abuf[2] = { sm, sm + ASZ };
    float* Bbuf[2] = { sm + 2 * ASZ, sm + 2 * ASZ + BSZ };
    float* sp = sm + 2 * ASZ + 2 * BSZ;
    float* sln = sp + 3 * DOUT;

    int t = threadIdx.x;
    int wid = t >> 5, lane = t & 31;
    int g = lane >> 2, tq = lane & 3;
    int mw = wid & 7, nh = wid >> 3;
    int nbase = nh * BNh;
    int row0 = blockIdx.x * 128;

    for (int i = t; i < DOUT; i += 512) {
        sp[i] = bias[i];
        sp[DOUT + i] = gamma[i];
        sp[2 * DOUT + i] = beta[i];
    }

    float acc[NT][4];
#pragma unroll
    for (int nt = 0; nt < NT; nt++)
#pragma unroll
        for (int j = 0; j < 4; j++) acc[nt][j] = 0.f;

    int sa_r[2], sa_k4[2];
#pragma unroll
    for (int i = 0; i < 2; i++) {
        int idx = t + i * 512;
        sa_r[i] = idx >> 3;
        sa_k4[i] = idx & 7;
    }
    int sb_kp = t & 3;
    int sb_n = t >> 2;

    float4 av[2];
    float bv0[4 * NP], bv1[4 * NP];

    auto ldg_chunk = [&](int c) {
        const float* A = (c < NCH) ? A0 : A1;
        const float* W = (c < NCH) ? W0 : W1;
        int k0 = ((c < NCH) ? c : c - NCH) * 32;
#pragma unroll
        for (int i = 0; i < 2; i++) {
            int gr = row0 + sa_r[i];
            float4 v = make_float4(0.f, 0.f, 0.f, 0.f);
            if (gr < n) v = *(const float4*)(A + (size_t)gr * DIN + k0 + sa_k4[i] * 4);
            av[i] = v;
        }
#pragma unroll
        for (int ks = 0; ks < 4; ks++)
#pragma unroll
            for (int np = 0; np < NP; np++) {
                int k = k0 + ks * 8 + sb_kp;
                int nn = sb_n + np * 128;
                bv0[ks * NP + np] = W[(size_t)k * DOUT + nn];
                bv1[ks * NP + np] = W[(size_t)(k + 4) * DOUT + nn];
            }
    };

    auto sts_chunk = [&](int b) {
        float* Af = Abuf[b];
#pragma unroll
        for (int i = 0; i < 2; i++) {
            int q = sa_k4[i] >> 1, e = sa_k4[i] & 1;
            int base = (q * 128 + sa_r[i]) * 8;
            float vals[4] = { av[i].x, av[i].y, av[i].z, av[i].w };
#pragma unroll
            for (int cc = 0; cc < 4; cc++)
                Af[base + ((cc ^ q) * 2 + e)] = __uint_as_float(tf32r(vals[cc]));
        }
        float2* Bu = (float2*)Bbuf[b];
#pragma unroll
        for (int ks = 0; ks < 4; ks++)
#pragma unroll
            for (int np = 0; np < NP; np++) {
                int nn = sb_n + np * 128;
                float2 p;
                p.x = __uint_as_float(tf32r(bv0[ks * NP + np]));
                p.y = __uint_as_float(tf32r(bv1[ks * NP + np]));
                Bu[(ks * DOUT + nn) * 4 + sb_kp] = p;
            }
    };

    auto mma_chunk = [&](int b) {
        const uint2* Au = (const uint2*)Abuf[b];
        const uint2* Bu = (const uint2*)Bbuf[b];
        int arow = mw * 16 + g;
#pragma unroll
        for (int ks = 0; ks < 4; ks++) {
            int kk = tq ^ ks;
            uint2 aA = Au[(ks * 128 + arow) * 4 + kk];
            uint2 aB = Au[(ks * 128 + arow + 8) * 4 + kk];
#pragma unroll
            for (int nt = 0; nt < NT; nt++) {
                uint2 bb = Bu[(ks * DOUT + nbase + nt * 8 + g) * 4 + tq];
                mma_tf32(acc[nt], aA.x, aB.x, aA.y, aB.y, bb.x, bb.y);
            }
        }
    };

    ldg_chunk(0);
    sts_chunk(0);
    __syncthreads();
    for (int c = 0; c < TOT; c++) {
        if (c + 1 < TOT) ldg_chunk(c + 1);
        mma_chunk(c & 1);
        if (c + 1 < TOT) sts_chunk((c + 1) & 1);
        __syncthreads();
    }

    float s0 = 0.f, ss0 = 0.f, s1 = 0.f, ss1 = 0.f;
#pragma unroll
    for (int nt = 0; nt < NT; nt++) {
        int col = nbase + nt * 8 + 2 * tq;
        float b0 = sp[col], b1 = sp[col + 1];
        acc[nt][0] += b0; acc[nt][1] += b1;
        acc[nt][2] += b0; acc[nt][3] += b1;
        s0 += acc[nt][0] + acc[nt][1];
        ss0 += acc[nt][0] * acc[nt][0] + acc[nt][1] * acc[nt][1];
        s1 += acc[nt][2] + acc[nt][3];
        ss1 += acc[nt][2] * acc[nt][2] + acc[nt][3] * acc[nt][3];
    }
#pragma unroll
    for (int o = 1; o <= 2; o <<= 1) {
        s0 += __shfl_xor_sync(0xffffffffu, s0, o);
        ss0 += __shfl_xor_sync(0xffffffffu, ss0, o);
        s1 += __shfl_xor_sync(0xffffffffu, s1, o);
        ss1 += __shfl_xor_sync(0xffffffffu, ss1, o);
    }
    int rl0 = mw * 16 + g, rl1 = rl0 + 8;
    if (tq == 0) {
        ((float2*)sln)[rl0 * 2 + nh] = make_float2(s0, ss0);
        ((float2*)sln)[rl1 * 2 + nh] = make_float2(s1, ss1);
    }
    __syncthreads();
    float2 p00 = ((float2*)sln)[rl0 * 2 + 0], p01 = ((float2*)sln)[rl0 * 2 + 1];
    float2 p10 = ((float2*)sln)[rl1 * 2 + 0], p11 = ((float2*)sln)[rl1 * 2 + 1];
    float mu0 = (p00.x + p01.x) * (1.0f / DOUT);
    float var0 = (p00.y + p01.y) * (1.0f / DOUT) - mu0 * mu0;
    float rs0 = rsqrtf(var0 + 1e-5f);
    float mu1 = (p10.x + p11.x) * (1.0f / DOUT);
    float var1 = (p10.y + p11.y) * (1.0f / DOUT) - mu1 * mu1;
    float rs1 = rsqrtf(var1 + 1e-5f);

    int grow0 = row0 + rl0, grow1 = row0 + rl1;
#pragma unroll
    for (int nt = 0; nt < NT; nt++) {
        int col = nbase + nt * 8 + 2 * tq;
        float ga0 = sp[DOUT + col], ga1 = sp[DOUT + col + 1];
        float bt0 = sp[2 * DOUT + col], bt1 = sp[2 * DOUT + col + 1];
        if (grow0 < n) {
            float2 v;
            v.x = fmaxf((acc[nt][0] - mu0) * rs0 * ga0 + bt0, 0.f);
            v.y = fmaxf((acc[nt][1] - mu0) * rs0 * ga1 + bt1, 0.f);
            *(float2*)(out + (size_t)grow0 * DOUT + col) = v;
        }
        if (grow1 < n) {
            float2 v;
            v.x = fmaxf((acc[nt][2] - mu1) * rs1 * ga0 + bt0, 0.f);
            v.y = fmaxf((acc[nt][3] - mu1) * rs1 * ga1 + bt1, 0.f);
            *(float2*)(out + (size_t)grow1 * DOUT + col) = v;
        }
    }
}

// ================= dual-output GEMM: YM = X@W0, YR = X@W1 + b (no LN) =================
// Single A (X); both weights staged per chunk. Used for aggregate-after layers.
template <int DIN, int DOUT>
__launch_bounds__(512, 1)
__global__ void k_gemm_dual(const float* __restrict__ X,
                            const float* __restrict__ W0, const float* __restrict__ W1,
                            const float* __restrict__ bias,
                            float* __restrict__ ym, float* __restrict__ yr, int n) {
    extern __shared__ float sm[];
    constexpr int NCH = DIN / 32;
    constexpr int NP = DOUT / 128;
    constexpr int BNh = DOUT / 2;
    constexpr int NT = BNh / 8;
    constexpr int ASZ = 128 * 32;
    constexpr int BSZ = DOUT * 32;

    float* Abuf[2] = { sm, sm + ASZ };
    float* B0buf[2] = { sm + 2 * ASZ, sm + 2 * ASZ + BSZ };
    float* B1buf[2] = { sm + 2 * ASZ + 2 * BSZ, sm + 2 * ASZ + 3 * BSZ };
    float* sp = sm + 2 * ASZ + 4 * BSZ;   // bias

    int t = threadIdx.x;
    int wid = t >> 5, lane = t & 31;
    int g = lane >> 2, tq = lane & 3;
    int mw = wid & 7, nh = wid >> 3;
    int nbase = nh * BNh;
    int row0 = blockIdx.x * 128;

    for (int i = t; i < DOUT; i += 512) sp[i] = bias[i];

    float accM[NT][4], accR[NT][4];
#pragma unroll
    for (int nt = 0; nt < NT; nt++)
#pragma unroll
        for (int j = 0; j < 4; j++) { accM[nt][j] = 0.f; accR[nt][j] = 0.f; }

    int sa_r[2], sa_k4[2];
#pragma unroll
    for (int i = 0; i < 2; i++) {
        int idx = t + i * 512;
        sa_r[i] = idx >> 3;
        sa_k4[i] = idx & 7;
    }
    int sb_kp = t & 3;
    int sb_n = t >> 2;

    float4 av[2];
    float bm0[4 * NP], bm1[4 * NP], br0[4 * NP], br1[4 * NP];

    auto ldg_chunk = [&](int c) {
        int k0 = c * 32;
#pragma unroll
        for (int i = 0; i < 2; i++) {
            int gr = row0 + sa_r[i];
            float4 v = make_float4(0.f, 0.f, 0.f, 0.f);
            if (gr < n) v = *(const float4*)(X + (size_t)gr * DIN + k0 + sa_k4[i] * 4);
            av[i] = v;
        }
#pragma unroll
        for (int ks = 0; ks < 4; ks++)
#pragma unroll
            for (int np = 0; np < NP; np++) {
                int k = k0 + ks * 8 + sb_kp;
                int nn = sb_n + np * 128;
                bm0[ks * NP + np] = W0[(size_t)k * DOUT + nn];
                bm1[ks * NP + np] = W0[(size_t)(k + 4) * DOUT + nn];
                br0[ks * NP + np] = W1[(size_t)k * DOUT + nn];
                br1[ks * NP + np] = W1[(size_t)(k + 4) * DOUT + nn];
            }
    };

    auto sts_chunk = [&](int b) {
        float* Af = Abuf[b];
#pragma unroll
        for (int i = 0; i < 2; i++) {
            int q = sa_k4[i] >> 1, e = sa_k4[i] & 1;
            int base = (q * 128 + sa_r[i]) * 8;
            float vals[4] = { av[i].x, av[i].y, av[i].z, av[i].w };
#pragma unroll
            for (int cc = 0; cc < 4; cc++)
                Af[base + ((cc ^ q) * 2 + e)] = __uint_as_float(tf32r(vals[cc]));
        }
        float2* B0u = (float2*)B0buf[b];
        float2* B1u = (float2*)B1buf[b];
#pragma unroll
        for (int ks = 0; ks < 4; ks++)
#pragma unroll
            for (int np = 0; np < NP; np++) {
                int nn = sb_n + np * 128;
                float2 p, q2;
                p.x = __uint_as_float(tf32r(bm0[ks * NP + np]));
                p.y = __uint_as_float(tf32r(bm1[ks * NP + np]));
                q2.x = __uint_as_float(tf32r(br0[ks * NP + np]));
                q2.y = __uint_as_float(tf32r(br1[ks * NP + np]));
                B0u[(ks * DOUT + nn) * 4 + sb_kp] = p;
                B1u[(ks * DOUT + nn) * 4 + sb_kp] = q2;
            }
    };

    auto mma_chunk = [&](int b) {
        const uint2* Au = (const uint2*)Abuf[b];
        const uint2* B0u = (const uint2*)B0buf[b];
        const uint2* B1u = (const uint2*)B1buf[b];
        int arow = mw * 16 + g;
#pragma unroll
        for (int ks = 0; ks < 4; ks++) {
            int kk = tq ^ ks;
            uint2 aA = Au[(ks * 128 + arow) * 4 + kk];
            uint2 aB = Au[(ks * 128 + arow + 8) * 4 + kk];
#pragma unroll
            for (int nt = 0; nt < NT; nt++) {
                int bi = (ks * DOUT + nbase + nt * 8 + g) * 4 + tq;
                uint2 b0 = B0u[bi];
                uint2 b1 = B1u[bi];
                mma_tf32(accM[nt], aA.x, aB.x, aA.y, aB.y, b0.x, b0.y);
                mma_tf32(accR[nt], aA.x, aB.x, aA.y, aB.y, b1.x, b1.y);
            }
        }
    };

    ldg_chunk(0);
    sts_chunk(0);
    __syncthreads();
    for (int c = 0; c < NCH; c++) {
        if (c + 1 < NCH) ldg_chunk(c + 1);
        mma_chunk(c & 1);
        if (c + 1 < NCH) sts_chunk((c + 1) & 1);
        __syncthreads();
    }

    int rl0 = mw * 16 + g, rl1 = rl0 + 8;
    int grow0 = row0 + rl0, grow1 = row0 + rl1;
#pragma unroll
    for (int nt = 0; nt < NT; nt++) {
        int col = nbase + nt * 8 + 2 * tq;
        float b0 = sp[col], b1 = sp[col + 1];
        if (grow0 < n) {
            *(float2*)(ym + (size_t)grow0 * DOUT + col) = make_float2(accM[nt][0], accM[nt][1]);
            *(float2*)(yr + (size_t)grow0 * DOUT + col) = make_float2(accR[nt][0] + b0, accR[nt][1] + b1);
        }
        if (grow1 < n) {
            *(float2*)(ym + (size_t)grow1 * DOUT + col) = make_float2(accM[nt][2], accM[nt][3]);
            *(float2*)(yr + (size_t)grow1 * DOUT + col) = make_float2(accR[nt][2] + b0, accR[nt][3] + b1);
        }
    }
}

// ================= elementwise: out = ReLU(LN(mean + yr)) , D=128, warp/row =================
__global__ void k_addlnrelu(const float* __restrict__ meanp, const float* __restrict__ yr,
                            const float* __restrict__ gamma, const float* __restrict__ beta,
                            float* __restrict__ out, int n) {
    int row = (blockIdx.x * blockDim.x + threadIdx.x) >> 5;
    int lane = threadIdx.x & 31;
    if (row >= n) return;
    float4 m4 = ((const float4*)(meanp + (size_t)row * 128))[lane];
    float4 y4 = ((const float4*)(yr + (size_t)row * 128))[lane];
    float v[4] = { m4.x + y4.x, m4.y + y4.y, m4.z + y4.z, m4.w + y4.w };
    float s = v[0] + v[1] + v[2] + v[3];
    float ss = v[0] * v[0] + v[1] * v[1] + v[2] * v[2] + v[3] * v[3];
#pragma unroll
    for (int o = 16; o; o >>= 1) {
        s += __shfl_xor_sync(0xffffffffu, s, o);
        ss += __shfl_xor_sync(0xffffffffu, ss, o);
    }
    float mu = s * (1.0f / 128.0f);
    float var = ss * (1.0f / 128.0f) - mu * mu;
    float rs = rsqrtf(var + 1e-5f);
    float4 g4 = ((const float4*)gamma)[lane];
    float4 b4 = ((const float4*)beta)[lane];
    float4 o4;
    o4.x = fmaxf((v[0] - mu) * rs * g4.x + b4.x, 0.f);
    o4.y = fmaxf((v[1] - mu) * rs * g4.y + b4.y, 0.f);
    o4.z = fmaxf((v[2] - mu) * rs * g4.z + b4.z, 0.f);
    o4.w = fmaxf((v[3] - mu) * rs * g4.w + b4.w, 0.f);
    ((float4*)(out + (size_t)row * 128))[lane] = o4;
}

// ================= final layer part 1: ym9 = x@Wm4, yr9 = x@Wr4 + b4 =================
__global__ void k_out_dual(const float* __restrict__ x,
                           const float* __restrict__ wm, const float* __restrict__ wr,
                           const float* __restrict__ bias,
                           float* __restrict__ ym9, float* __restrict__ yr9, int n) {
    __shared__ float swm[128 * 9];
    __shared__ float swr[128 * 9];
    __shared__ float sb[9];
    for (int i = threadIdx.x; i < 128 * 9; i += blockDim.x) {
        swm[i] = wm[i];
        swr[i] = wr[i];
    }
    if (threadIdx.x < 9) sb[threadIdx.x] = bias[threadIdx.x];
    __syncthreads();

    int gw = (blockIdx.x * blockDim.x + threadIdx.x) >> 5;
    int lane = threadIdx.x & 31;
    if (gw >= n) return;

    float4 ax = ((const float4*)(x + (size_t)gw * 128))[lane];
    float x4[4] = { ax.x, ax.y, ax.z, ax.w };

    float om[9], orr[9];
#pragma unroll
    for (int j = 0; j < 9; j++) { om[j] = 0.f; orr[j] = 0.f; }
#pragma unroll
    for (int q = 0; q < 4; q++) {
        int k = lane * 4 + q;
#pragma unroll
        for (int j = 0; j < 9; j++) {
            om[j] += x4[q] * swm[k * 9 + j];
            orr[j] += x4[q] * swr[k * 9 + j];
        }
    }
#pragma unroll
    for (int j = 0; j < 9; j++)
#pragma unroll
        for (int s = 16; s; s >>= 1) {
            om[j] += __shfl_xor_sync(0xffffffffu, om[j], s);
            orr[j] += __shfl_xor_sync(0xffffffffu, orr[j], s);
        }
    if (lane < 9) {
        ym9[(size_t)gw * 9 + lane] = om[lane];
        yr9[(size_t)gw * 9 + lane] = orr[lane] + sb[lane];
    }
}

// ================= final layer part 2: out = mean(ym9[src]) + yr9 =================
__global__ void k_agg9(const float* __restrict__ ym9, const float* __restrict__ yr9,
                       float* __restrict__ out, int n) {
    int gw = (blockIdx.x * blockDim.x + threadIdx.x) >> 5;
    int lane = threadIdx.x & 31;
    if (gw >= n) return;
    int b = g_off[gw], e = g_off[gw + 1];
    float acc[9];
#pragma unroll
    for (int j = 0; j < 9; j++) acc[j] = 0.f;
    for (int j = b + lane; j < e; j += 32) {
        const float* row = ym9 + (size_t)g_csr[j] * 9;
#pragma unroll
        for (int c = 0; c < 9; c++) acc[c] += row[c];
    }
#pragma unroll
    for (int c = 0; c < 9; c++)
#pragma unroll
        for (int s = 16; s; s >>= 1) acc[c] += __shfl_xor_sync(0xffffffffu, acc[c], s);
    if (lane < 9) {
        float inv = 1.0f / g_cnt[gw];
        out[(size_t)gw * 9 + lane] = acc[lane] * inv + yr9[(size_t)gw * 9 + lane];
    }
}

// ================= launch =================
extern "C" void kernel_launch(void* const* d_in, const int* in_sizes, int n_in,
                              void* d_out, int out_size) {
    const float* z = (const float*)d_in[0];
    const int* ei = (const int*)d_in[1];
    const float* wm1 = (const float*)d_in[2];
    const float* wr1 = (const float*)d_in[3];
    const float* b1 = (const float*)d_in[4];
    const float* g1 = (const float*)d_in[5];
    const float* be1 = (const float*)d_in[6];
    const float* wm2 = (const float*)d_in[7];
    const float* wr2 = (const float*)d_in[8];
    const float* b2 = (const float*)d_in[9];
    const float* g2 = (const float*)d_in[10];
    const float* be2 = (const float*)d_in[11];
    const float* wm3 = (const float*)d_in[12];
    const float* wr3 = (const float*)d_in[13];
    const float* b3 = (const float*)d_in[14];
    const float* g3 = (const float*)d_in[15];
    const float* be3 = (const float*)d_in[16];
    const float* wm4 = (const float*)d_in[17];
    const float* wr4 = (const float*)d_in[18];
    const float* b4 = (const float*)d_in[19];

    int N = in_sizes[0] / 128;
    int E = in_sizes[1] / 2;
    const int* src = ei;
    const int* dst = ei + E;

    float *bufA, *bufB, *meanb, *ym9, *yr9;
    void* p;
    cudaGetSymbolAddress(&p, g_bufA);  bufA = (float*)p;
    cudaGetSymbolAddress(&p, g_bufB);  bufB = (float*)p;
    cudaGetSymbolAddress(&p, g_meanb); meanb = (float*)p;
    cudaGetSymbolAddress(&p, g_ym9);   ym9 = (float*)p;
    cudaGetSymbolAddress(&p, g_yr9);   yr9 = (float*)p;

    const int SM256 = (8192 + 2 * 256 * 32 + 3 * 256 + 512) * 4;
    const int SMD128 = (8192 + 4 * 128 * 32 + 128) * 4;
    cudaFuncSetAttribute(k_gemm_tc<128, 256>, cudaFuncAttributeMaxDynamicSharedMemorySize, SM256);
    cudaFuncSetAttribute(k_gemm_tc<256, 256>, cudaFuncAttributeMaxDynamicSharedMemorySize, SM256);
    cudaFuncSetAttribute(k_gemm_dual<256, 128>, cudaFuncAttributeMaxDynamicSharedMemorySize, SMD128);

    // CSR build (deterministic after segment sort)
    k_zero<<<(N + 255) / 256, 256>>>(N);
    k_hist<<<(E + 255) / 256, 256>>>(dst, E);
    k_scan<<<1, 1024>>>(N);
    k_scatter<<<(E + 255) / 256, 256>>>(src, dst, E);
    k_sortseg<<<(N + 255) / 256, 256>>>(N);

    int aggBlocks = (N + 7) / 8;
    int gemmBlocks = (N + 127) / 128;

    // Layer 1: 128 -> 256 (aggregate-first)
    k_agg<128><<<aggBlocks, 256>>>(z, meanb, N);
    k_gemm_tc<128, 256><<<gemmBlocks, 512, SM256>>>(meanb, z, wm1, wr1, b1, g1, be1, bufA, N);
    // Layer 2: 256 -> 256 (aggregate-first)
    k_agg<256><<<aggBlocks, 256>>>(bufA, meanb, N);
    k_gemm_tc<256, 256><<<gemmBlocks, 512, SM256>>>(meanb, bufA, wm2, wr2, b2, g2, be2, bufB, N);
    // Layer 3: 256 -> 128 (aggregate-AFTER: gather 128 instead of 256)
    k_gemm_dual<256, 128><<<gemmBlocks, 512, SMD128>>>(bufB, wm3, wr3, b3, meanb, bufA, N);
    k_agg<128><<<aggBlocks, 256>>>(meanb, bufB, N);            // mean of ym3
    k_addlnrelu<<<aggBlocks, 256>>>(bufB, bufA, g3, be3, meanb, N);  // x3 -> meanb
    // Layer 4: 128 -> 9 (aggregate-AFTER: gather 9 instead of 128)
    k_out_dual<<<aggBlocks, 256>>>(meanb, wm4, wr4, b4, ym9, yr9, N);
    k_agg9<<<aggBlocks, 256>>>(ym9, yr9, (float*)d_out, N);
}

// round 7
// speedup vs baseline: 1.7775x; 1.0136x over previous
#include <cuda_runtime.h>
#include <cstdint>

// ================= static scratch =================
#define NMAX 100352
#define EMAX 1700000

__device__ int   g_deg[NMAX];     // zero at load; re-zeroed by k_agg9 each launch
__device__ int   g_off[NMAX + 1];
__device__ int   g_cur[NMAX];
__device__ int   g_csr[EMAX];
__device__ float g_cnt[NMAX];
__device__ float g_bufA[(size_t)NMAX * 256];
__device__ float g_bufB[(size_t)NMAX * 256];
__device__ float g_meanb[(size_t)NMAX * 256];
__device__ float g_ym9[(size_t)NMAX * 9];
__device__ float g_yr9[(size_t)NMAX * 9];

// ================= helpers =================
__device__ __forceinline__ uint32_t tf32r(float f) {
    uint32_t u;
    asm("cvt.rna.tf32.f32 %0, %1;" : "=r"(u) : "f"(f));
    return u;
}
__device__ __forceinline__ void mma_tf32(float* c, uint32_t a0, uint32_t a1, uint32_t a2, uint32_t a3,
                                         uint32_t b0, uint32_t b1) {
    asm volatile("mma.sync.aligned.m16n8k8.row.col.f32.tf32.tf32.f32 "
                 "{%0,%1,%2,%3}, {%4,%5,%6,%7}, {%8,%9}, {%0,%1,%2,%3};"
                 : "+f"(c[0]), "+f"(c[1]), "+f"(c[2]), "+f"(c[3])
                 : "r"(a0), "r"(a1), "r"(a2), "r"(a3), "r"(b0), "r"(b1));
}

// ================= CSR build =================
__global__ void k_hist(const int* __restrict__ dst, int E) {
    int e = blockIdx.x * blockDim.x + threadIdx.x;
    if (e < E) atomicAdd(&g_deg[dst[e]], 1);
}
__global__ void k_scan(int n) {
    __shared__ int part[1024];
    int t = threadIdx.x;
    int chunk = (n + 1023) / 1024;
    int beg = t * chunk;
    int end = min(beg + chunk, n);
    int s = 0;
    for (int i = beg; i < end; i++) s += g_deg[i];
    part[t] = s;
    __syncthreads();
    for (int off = 1; off < 1024; off <<= 1) {
        int v = (t >= off) ? part[t - off] : 0;
        __syncthreads();
        part[t] += v;
        __syncthreads();
    }
    int run = (t == 0) ? 0 : part[t - 1];
    for (int i = beg; i < end; i++) {
        int d = g_deg[i];
        g_off[i] = run;
        g_cur[i] = run;
        g_cnt[i] = (d > 0) ? (float)d : 1.0f;
        run += d;
    }
    if (end == n) g_off[n] = run;
}
__global__ void k_scatter(const int* __restrict__ src, const int* __restrict__ dst, int E) {
    int e = blockIdx.x * blockDim.x + threadIdx.x;
    if (e < E) {
        int p = atomicAdd(&g_cur[dst[e]], 1);
        g_csr[p] = src[e];
    }
}

// ================= mean aggregation: one warp per node (2x edge unroll) =================
template <int D>
__global__ void k_agg(const float* __restrict__ x, float* __restrict__ meanp, int n) {
    int gw = (blockIdx.x * blockDim.x + threadIdx.x) >> 5;
    int lane = threadIdx.x & 31;
    if (gw >= n) return;
    int b = g_off[gw], e = g_off[gw + 1];
    constexpr int IT = D / 128;
    float4 acc[IT], acc2[IT];
#pragma unroll
    for (int it = 0; it < IT; it++) {
        acc[it] = make_float4(0.f, 0.f, 0.f, 0.f);
        acc2[it] = make_float4(0.f, 0.f, 0.f, 0.f);
    }
    int j = b;
    for (; j + 1 < e; j += 2) {
        const float4* r0 = (const float4*)(x + (size_t)g_csr[j] * D);
        const float4* r1 = (const float4*)(x + (size_t)g_csr[j + 1] * D);
#pragma unroll
        for (int it = 0; it < IT; it++) {
            float4 v0 = r0[lane + it * 32];
            float4 v1 = r1[lane + it * 32];
            acc[it].x += v0.x; acc[it].y += v0.y; acc[it].z += v0.z; acc[it].w += v0.w;
            acc2[it].x += v1.x; acc2[it].y += v1.y; acc2[it].z += v1.z; acc2[it].w += v1.w;
        }
    }
    if (j < e) {
        const float4* r0 = (const float4*)(x + (size_t)g_csr[j] * D);
#pragma unroll
        for (int it = 0; it < IT; it++) {
            float4 v0 = r0[lane + it * 32];
            acc[it].x += v0.x; acc[it].y += v0.y; acc[it].z += v0.z; acc[it].w += v0.w;
        }
    }
    float inv = 1.0f / g_cnt[gw];
    float4* mo = (float4*)(meanp + (size_t)gw * D);
#pragma unroll
    for (int it = 0; it < IT; it++) {
        float4 v = acc[it];
        v.x = (v.x + acc2[it].x) * inv;
        v.y = (v.y + acc2[it].y) * inv;
        v.z = (v.z + acc2[it].z) * inv;
        v.w = (v.w + acc2[it].w) * inv;
        mo[lane + it * 32] = v;
    }
}

// ================= tf32 mma fused dual-GEMM + bias + LN + ReLU =================
// out[128 x DOUT] = LNReLU( A0 @ W0 + A1 @ W1 + b ).
// 512 threads = 16 warps as Wm=4 x Wn=4. Warp covers 32 rows (2 m16 subtiles)
// x DOUT/4 cols (NT=DOUT/32 n-tiles). B frag loaded once per (ks,nt), used by
// both m-subtiles -> 33% less smem crossbar traffic; acc small enough to hoist
// B fragments (no LDS->HMMA serialization).
template <int DIN, int DOUT>
__launch_bounds__(512)
__global__ void k_gemm_tc(const float* __restrict__ A0, const float* __restrict__ A1,
                          const float* __restrict__ W0, const float* __restrict__ W1,
                          const float* __restrict__ bias, const float* __restrict__ gamma,
                          const float* __restrict__ beta, float* __restrict__ out, int n) {
    extern __shared__ float sm[];
    constexpr int NCH = DIN / 32;
    constexpr int TOT = 2 * NCH;
    constexpr int NP = DOUT / 128;
    constexpr int NT = DOUT / 32;
    constexpr int ASZ = 128 * 32;
    constexpr int BSZ = DOUT * 32;

    float* Abuf[2] = { sm, sm + ASZ };
    float* Bbuf[2] = { sm + 2 * ASZ, sm + 2 * ASZ + BSZ };
    float* sp = sm + 2 * ASZ + 2 * BSZ;         // bias|gamma|beta
    float* sln = sp + 3 * DOUT;                  // [128][4] float2

    int t = threadIdx.x;
    int wid = t >> 5, lane = t & 31;
    int g = lane >> 2, tq = lane & 3;
    int mw = wid & 3, nq = wid >> 2;
    int nbase = nq * (DOUT / 4);
    int row0 = blockIdx.x * 128;

    for (int i = t; i < DOUT; i += 512) {
        sp[i] = bias[i];
        sp[DOUT + i] = gamma[i];
        sp[2 * DOUT + i] = beta[i];
    }

    float acc[2][NT][4];
#pragma unroll
    for (int ms = 0; ms < 2; ms++)
#pragma unroll
        for (int nt = 0; nt < NT; nt++)
#pragma unroll
            for (int j = 0; j < 4; j++) acc[ms][nt][j] = 0.f;

    int sa_r[2], sa_k4[2];
#pragma unroll
    for (int i = 0; i < 2; i++) {
        int idx = t + i * 512;
        sa_r[i] = idx >> 3;
        sa_k4[i] = idx & 7;
    }
    int sb_kp = t & 3;
    int sb_n = t >> 2;

    float4 av[2];
    float bv0[4 * NP], bv1[4 * NP];

    auto ldg_chunk = [&](int c) {
        const float* A = (c < NCH) ? A0 : A1;
        const float* W = (c < NCH) ? W0 : W1;
        int k0 = ((c < NCH) ? c : c - NCH) * 32;
#pragma unroll
        for (int i = 0; i < 2; i++) {
            int gr = row0 + sa_r[i];
            float4 v = make_float4(0.f, 0.f, 0.f, 0.f);
            if (gr < n) v = *(const float4*)(A + (size_t)gr * DIN + k0 + sa_k4[i] * 4);
            av[i] = v;
        }
#pragma unroll
        for (int ks = 0; ks < 4; ks++)
#pragma unroll
            for (int np = 0; np < NP; np++) {
                int k = k0 + ks * 8 + sb_kp;
                int nn = sb_n + np * 128;
                bv0[ks * NP + np] = W[(size_t)k * DOUT + nn];
                bv1[ks * NP + np] = W[(size_t)(k + 4) * DOUT + nn];
            }
    };

    auto sts_chunk = [&](int b) {
        float* Af = Abuf[b];
#pragma unroll
        for (int i = 0; i < 2; i++) {
            int q = sa_k4[i] >> 1, e = sa_k4[i] & 1;
            int base = (q * 128 + sa_r[i]) * 8;
            float vals[4] = { av[i].x, av[i].y, av[i].z, av[i].w };
#pragma unroll
            for (int cc = 0; cc < 4; cc++)
                Af[base + ((cc ^ q) * 2 + e)] = __uint_as_float(tf32r(vals[cc]));
        }
        float2* Bu = (float2*)Bbuf[b];
#pragma unroll
        for (int ks = 0; ks < 4; ks++)
#pragma unroll
            for (int np = 0; np < NP; np++) {
                int nn = sb_n + np * 128;
                float2 p;
                p.x = __uint_as_float(tf32r(bv0[ks * NP + np]));
                p.y = __uint_as_float(tf32r(bv1[ks * NP + np]));
                Bu[(ks * DOUT + nn) * 4 + sb_kp] = p;
            }
    };

    auto mma_chunk = [&](int b) {
        const uint2* Au = (const uint2*)Abuf[b];
        const uint2* Bu = (const uint2*)Bbuf[b];
#pragma unroll
        for (int ks = 0; ks < 4; ks++) {
            int kk = tq ^ ks;
            uint2 bfr[NT];
#pragma unroll
            for (int nt = 0; nt < NT; nt++)
                bfr[nt] = Bu[(ks * DOUT + nbase + nt * 8 + g) * 4 + tq];
#pragma unroll
            for (int ms = 0; ms < 2; ms++) {
                int arow = mw * 32 + ms * 16 + g;
                uint2 aA = Au[(ks * 128 + arow) * 4 + kk];
                uint2 aB = Au[(ks * 128 + arow + 8) * 4 + kk];
#pragma unroll
                for (int nt = 0; nt < NT; nt++)
                    mma_tf32(acc[ms][nt], aA.x, aB.x, aA.y, aB.y, bfr[nt].x, bfr[nt].y);
            }
        }
    };

    ldg_chunk(0);
    sts_chunk(0);
    __syncthreads();
    for (int c = 0; c < TOT; c++) {
        if (c + 1 < TOT) ldg_chunk(c + 1);
        mma_chunk(c & 1);
        if (c + 1 < TOT) sts_chunk((c + 1) & 1);
        __syncthreads();
    }

    // ---- epilogue: +bias, LN over DOUT (4 n-quarter partials), ReLU ----
#pragma unroll
    for (int ms = 0; ms < 2; ms++) {
        float s0 = 0.f, ss0 = 0.f, s1 = 0.f, ss1 = 0.f;
#pragma unroll
        for (int nt = 0; nt < NT; nt++) {
            int col = nbase + nt * 8 + 2 * tq;
            float b0 = sp[col], b1 = sp[col + 1];
            acc[ms][nt][0] += b0; acc[ms][nt][1] += b1;
            acc[ms][nt][2] += b0; acc[ms][nt][3] += b1;
            s0 += acc[ms][nt][0] + acc[ms][nt][1];
            ss0 += acc[ms][nt][0] * acc[ms][nt][0] + acc[ms][nt][1] * acc[ms][nt][1];
            s1 += acc[ms][nt][2] + acc[ms][nt][3];
            ss1 += acc[ms][nt][2] * acc[ms][nt][2] + acc[ms][nt][3] * acc[ms][nt][3];
        }
#pragma unroll
        for (int o = 1; o <= 2; o <<= 1) {
            s0 += __shfl_xor_sync(0xffffffffu, s0, o);
            ss0 += __shfl_xor_sync(0xffffffffu, ss0, o);
            s1 += __shfl_xor_sync(0xffffffffu, s1, o);
            ss1 += __shfl_xor_sync(0xffffffffu, ss1, o);
        }
        if (tq == 0) {
            int r0 = mw * 32 + ms * 16 + g;
            ((float2*)sln)[r0 * 4 + nq] = make_float2(s0, ss0);
            ((float2*)sln)[(r0 + 8) * 4 + nq] = make_float2(s1, ss1);
        }
    }
    __syncthreads();
#pragma unroll
    for (int ms = 0; ms < 2; ms++) {
        int rl0 = mw * 32 + ms * 16 + g, rl1 = rl0 + 8;
        float s0 = 0.f, ss0 = 0.f, s1 = 0.f, ss1 = 0.f;
#pragma unroll
        for (int q = 0; q < 4; q++) {
            float2 p0 = ((float2*)sln)[rl0 * 4 + q];
            float2 p1 = ((float2*)sln)[rl1 * 4 + q];
            s0 += p0.x; ss0 += p0.y;
            s1 += p1.x; ss1 += p1.y;
        }
        float mu0 = s0 * (1.0f / DOUT);
        float rs0 = rsqrtf(ss0 * (1.0f / DOUT) - mu0 * mu0 + 1e-5f);
        float mu1 = s1 * (1.0f / DOUT);
        float rs1 = rsqrtf(ss1 * (1.0f / DOUT) - mu1 * mu1 + 1e-5f);
        int grow0 = row0 + rl0, grow1 = row0 + rl1;
#pragma unroll
        for (int nt = 0; nt < NT; nt++) {
            int col = nbase + nt * 8 + 2 * tq;
            float ga0 = sp[DOUT + col], ga1 = sp[DOUT + col + 1];
            float bt0 = sp[2 * DOUT + col], bt1 = sp[2 * DOUT + col + 1];
            if (grow0 < n) {
                float2 v;
                v.x = fmaxf((acc[ms][nt][0] - mu0) * rs0 * ga0 + bt0, 0.f);
                v.y = fmaxf((acc[ms][nt][1] - mu0) * rs0 * ga1 + bt1, 0.f);
                *(float2*)(out + (size_t)grow0 * DOUT + col) = v;
            }
            if (grow1 < n) {
                float2 v;
                v.x = fmaxf((acc[ms][nt][2] - mu1) * rs1 * ga0 + bt0, 0.f);
                v.y = fmaxf((acc[ms][nt][3] - mu1) * rs1 * ga1 + bt1, 0.f);
                *(float2*)(out + (size_t)grow1 * DOUT + col) = v;
            }
        }
    }
}

// ================= dual-output GEMM: YM = X@W0, YR = X@W1 + b =================
template <int DIN, int DOUT>
__launch_bounds__(512)
__global__ void k_gemm_dual(const float* __restrict__ X,
                            const float* __restrict__ W0, const float* __restrict__ W1,
                            const float* __restrict__ bias,
                            float* __restrict__ ym, float* __restrict__ yr, int n) {
    extern __shared__ float sm[];
    constexpr int NCH = DIN / 32;
    constexpr int NP = DOUT / 128;
    constexpr int NT = DOUT / 32;
    constexpr int ASZ = 128 * 32;
    constexpr int BSZ = DOUT * 32;

    float* Abuf[2] = { sm, sm + ASZ };
    float* B0buf[2] = { sm + 2 * ASZ, sm + 2 * ASZ + BSZ };
    float* B1buf[2] = { sm + 2 * ASZ + 2 * BSZ, sm + 2 * ASZ + 3 * BSZ };
    float* sp = sm + 2 * ASZ + 4 * BSZ;

    int t = threadIdx.x;
    int wid = t >> 5, lane = t & 31;
    int g = lane >> 2, tq = lane & 3;
    int mw = wid & 3, nq = wid >> 2;
    int nbase = nq * (DOUT / 4);
    int row0 = blockIdx.x * 128;

    for (int i = t; i < DOUT; i += 512) sp[i] = bias[i];

    float accM[2][NT][4], accR[2][NT][4];
#pragma unroll
    for (int ms = 0; ms < 2; ms++)
#pragma unroll
        for (int nt = 0; nt < NT; nt++)
#pragma unroll
            for (int j = 0; j < 4; j++) { accM[ms][nt][j] = 0.f; accR[ms][nt][j] = 0.f; }

    int sa_r[2], sa_k4[2];
#pragma unroll
    for (int i = 0; i < 2; i++) {
        int idx = t + i * 512;
        sa_r[i] = idx >> 3;
        sa_k4[i] = idx & 7;
    }
    int sb_kp = t & 3;
    int sb_n = t >> 2;

    float4 av[2];
    float bm0[4 * NP], bm1[4 * NP], br0[4 * NP], br1[4 * NP];

    auto ldg_chunk = [&](int c) {
        int k0 = c * 32;
#pragma unroll
        for (int i = 0; i < 2; i++) {
            int gr = row0 + sa_r[i];
            float4 v = make_float4(0.f, 0.f, 0.f, 0.f);
            if (gr < n) v = *(const float4*)(X + (size_t)gr * DIN + k0 + sa_k4[i] * 4);
            av[i] = v;
        }
#pragma unroll
        for (int ks = 0; ks < 4; ks++)
#pragma unroll
            for (int np = 0; np < NP; np++) {
                int k = k0 + ks * 8 + sb_kp;
                int nn = sb_n + np * 128;
                bm0[ks * NP + np] = W0[(size_t)k * DOUT + nn];
                bm1[ks * NP + np] = W0[(size_t)(k + 4) * DOUT + nn];
                br0[ks * NP + np] = W1[(size_t)k * DOUT + nn];
                br1[ks * NP + np] = W1[(size_t)(k + 4) * DOUT + nn];
            }
    };

    auto sts_chunk = [&](int b) {
        float* Af = Abuf[b];
#pragma unroll
        for (int i = 0; i < 2; i++) {
            int q = sa_k4[i] >> 1, e = sa_k4[i] & 1;
            int base = (q * 128 + sa_r[i]) * 8;
            float vals[4] = { av[i].x, av[i].y, av[i].z, av[i].w };
#pragma unroll
            for (int cc = 0; cc < 4; cc++)
                Af[base + ((cc ^ q) * 2 + e)] = __uint_as_float(tf32r(vals[cc]));
        }
        float2* B0u = (float2*)B0buf[b];
        float2* B1u = (float2*)B1buf[b];
#pragma unroll
        for (int ks = 0; ks < 4; ks++)
#pragma unroll
            for (int np = 0; np < NP; np++) {
                int nn = sb_n + np * 128;
                float2 p, q2;
                p.x = __uint_as_float(tf32r(bm0[ks * NP + np]));
                p.y = __uint_as_float(tf32r(bm1[ks * NP + np]));
                q2.x = __uint_as_float(tf32r(br0[ks * NP + np]));
                q2.y = __uint_as_float(tf32r(br1[ks * NP + np]));
                B0u[(ks * DOUT + nn) * 4 + sb_kp] = p;
                B1u[(ks * DOUT + nn) * 4 + sb_kp] = q2;
            }
    };

    auto mma_chunk = [&](int b) {
        const uint2* Au = (const uint2*)Abuf[b];
        const uint2* B0u = (const uint2*)B0buf[b];
        const uint2* B1u = (const uint2*)B1buf[b];
#pragma unroll
        for (int ks = 0; ks < 4; ks++) {
            int kk = tq ^ ks;
            uint2 bfM[NT], bfR[NT];
#pragma unroll
            for (int nt = 0; nt < NT; nt++) {
                int bi = (ks * DOUT + nbase + nt * 8 + g) * 4 + tq;
                bfM[nt] = B0u[bi];
                bfR[nt] = B1u[bi];
            }
#pragma unroll
            for (int ms = 0; ms < 2; ms++) {
                int arow = mw * 32 + ms * 16 + g;
                uint2 aA = Au[(ks * 128 + arow) * 4 + kk];
                uint2 aB = Au[(ks * 128 + arow + 8) * 4 + kk];
#pragma unroll
                for (int nt = 0; nt < NT; nt++) {
                    mma_tf32(accM[ms][nt], aA.x, aB.x, aA.y, aB.y, bfM[nt].x, bfM[nt].y);
                    mma_tf32(accR[ms][nt], aA.x, aB.x, aA.y, aB.y, bfR[nt].x, bfR[nt].y);
                }
            }
        }
    };

    ldg_chunk(0);
    sts_chunk(0);
    __syncthreads();
    for (int c = 0; c < NCH; c++) {
        if (c + 1 < NCH) ldg_chunk(c + 1);
        mma_chunk(c & 1);
        if (c + 1 < NCH) sts_chunk((c + 1) & 1);
        __syncthreads();
    }

#pragma unroll
    for (int ms = 0; ms < 2; ms++) {
        int rl0 = mw * 32 + ms * 16 + g, rl1 = rl0 + 8;
        int grow0 = row0 + rl0, grow1 = row0 + rl1;
#pragma unroll
        for (int nt = 0; nt < NT; nt++) {
            int col = nbase + nt * 8 + 2 * tq;
            float b0 = sp[col], b1 = sp[col + 1];
            if (grow0 < n) {
                *(float2*)(ym + (size_t)grow0 * DOUT + col) = make_float2(accM[ms][nt][0], accM[ms][nt][1]);
                *(float2*)(yr + (size_t)grow0 * DOUT + col) = make_float2(accR[ms][nt][0] + b0, accR[ms][nt][1] + b1);
            }
            if (grow1 < n) {
                *(float2*)(ym + (size_t)grow1 * DOUT + col) = make_float2(accM[ms][nt][2], accM[ms][nt][3]);
                *(float2*)(yr + (size_t)grow1 * DOUT + col) = make_float2(accR[ms][nt][2] + b0, accR[ms][nt][3] + b1);
            }
        }
    }
}

// ================= elementwise: out = ReLU(LN(mean + yr)), D=128, warp/row =================
__global__ void k_addlnrelu(const float* __restrict__ meanp, const float* __restrict__ yr,
                            const float* __restrict__ gamma, const float* __restrict__ beta,
                            float* __restrict__ out, int n) {
    int row = (blockIdx.x * blockDim.x + threadIdx.x) >> 5;
    int lane = threadIdx.x & 31;
    if (row >= n) return;
    float4 m4 = ((const float4*)(meanp + (size_t)row * 128))[lane];
    float4 y4 = ((const float4*)(yr + (size_t)row * 128))[lane];
    float v[4] = { m4.x + y4.x, m4.y + y4.y, m4.z + y4.z, m4.w + y4.w };
    float s = v[0] + v[1] + v[2] + v[3];
    float ss = v[0] * v[0] + v[1] * v[1] + v[2] * v[2] + v[3] * v[3];
#pragma unroll
    for (int o = 16; o; o >>= 1) {
        s += __shfl_xor_sync(0xffffffffu, s, o);
        ss += __shfl_xor_sync(0xffffffffu, ss, o);
    }
    float mu = s * (1.0f / 128.0f);
    float var = ss * (1.0f / 128.0f) - mu * mu;
    float rs = rsqrtf(var + 1e-5f);
    float4 g4 = ((const float4*)gamma)[lane];
    float4 b4 = ((const float4*)beta)[lane];
    float4 o4;
    o4.x = fmaxf((v[0] - mu) * rs * g4.x + b4.x, 0.f);
    o4.y = fmaxf((v[1] - mu) * rs * g4.y + b4.y, 0.f);
    o4.z = fmaxf((v[2] - mu) * rs * g4.z + b4.z, 0.f);
    o4.w = fmaxf((v[3] - mu) * rs * g4.w + b4.w, 0.f);
    ((float4*)(out + (size_t)row * 128))[lane] = o4;
}

// ================= final layer part 1: ym9 = x@Wm4, yr9 = x@Wr4 + b4 =================
__global__ void k_out_dual(const float* __restrict__ x,
                           const float* __restrict__ wm, const float* __restrict__ wr,
                           const float* __restrict__ bias,
                           float* __restrict__ ym9, float* __restrict__ yr9, int n) {
    __shared__ float swm[128 * 9];
    __shared__ float swr[128 * 9];
    __shared__ float sb[9];
    for (int i = threadIdx.x; i < 128 * 9; i += blockDim.x) {
        swm[i] = wm[i];
        swr[i] = wr[i];
    }
    if (threadIdx.x < 9) sb[threadIdx.x] = bias[threadIdx.x];
    __syncthreads();

    int gw = (blockIdx.x * blockDim.x + threadIdx.x) >> 5;
    int lane = threadIdx.x & 31;
    if (gw >= n) return;

    float4 ax = ((const float4*)(x + (size_t)gw * 128))[lane];
    float x4[4] = { ax.x, ax.y, ax.z, ax.w };

    float om[9], orr[9];
#pragma unroll
    for (int j = 0; j < 9; j++) { om[j] = 0.f; orr[j] = 0.f; }
#pragma unroll
    for (int q = 0; q < 4; q++) {
        int k = lane * 4 + q;
#pragma unroll
        for (int j = 0; j < 9; j++) {
            om[j] += x4[q] * swm[k * 9 + j];
            orr[j] += x4[q] * swr[k * 9 + j];
        }
    }
#pragma unroll
    for (int j = 0; j < 9; j++)
#pragma unroll
        for (int s = 16; s; s >>= 1) {
            om[j] += __shfl_xor_sync(0xffffffffu, om[j], s);
            orr[j] += __shfl_xor_sync(0xffffffffu, orr[j], s);
        }
    if (lane < 9) {
        ym9[(size_t)gw * 9 + lane] = om[lane];
        yr9[(size_t)gw * 9 + lane] = orr[lane] + sb[lane];
    }
}

// ================= final layer part 2: out = mean(ym9[src]) + yr9; re-zero g_deg =================
__global__ void k_agg9(const float* __restrict__ ym9, const float* __restrict__ yr9,
                       float* __restrict__ out, int n) {
    int gt = blockIdx.x * blockDim.x + threadIdx.x;
    if (gt < NMAX) g_deg[gt] = 0;    // prepare next launch's k_hist
    int gw = gt >> 5;
    int lane = threadIdx.x & 31;
    if (gw >= n) return;
    int b = g_off[gw], e = g_off[gw + 1];
    float acc[9];
#pragma unroll
    for (int j = 0; j < 9; j++) acc[j] = 0.f;
    for (int j = b + lane; j < e; j += 32) {
        const float* row = ym9 + (size_t)g_csr[j] * 9;
#pragma unroll
        for (int c = 0; c < 9; c++) acc[c] += row[c];
    }
#pragma unroll
    for (int c = 0; c < 9; c++)
#pragma unroll
        for (int s = 16; s; s >>= 1) acc[c] += __shfl_xor_sync(0xffffffffu, acc[c], s);
    if (lane < 9) {
        float inv = 1.0f / g_cnt[gw];
        out[(size_t)gw * 9 + lane] = acc[lane] * inv + yr9[(size_t)gw * 9 + lane];
    }
}

// ================= launch =================
extern "C" void kernel_launch(void* const* d_in, const int* in_sizes, int n_in,
                              void* d_out, int out_size) {
    const float* z = (const float*)d_in[0];
    const int* ei = (const int*)d_in[1];
    const float* wm1 = (const float*)d_in[2];
    const float* wr1 = (const float*)d_in[3];
    const float* b1 = (const float*)d_in[4];
    const float* g1 = (const float*)d_in[5];
    const float* be1 = (const float*)d_in[6];
    const float* wm2 = (const float*)d_in[7];
    const float* wr2 = (const float*)d_in[8];
    const float* b2 = (const float*)d_in[9];
    const float* g2 = (const float*)d_in[10];
    const float* be2 = (const float*)d_in[11];
    const float* wm3 = (const float*)d_in[12];
    const float* wr3 = (const float*)d_in[13];
    const float* b3 = (const float*)d_in[14];
    const float* g3 = (const float*)d_in[15];
    const float* be3 = (const float*)d_in[16];
    const float* wm4 = (const float*)d_in[17];
    const float* wr4 = (const float*)d_in[18];
    const float* b4 = (const float*)d_in[19];

    int N = in_sizes[0] / 128;
    int E = in_sizes[1] / 2;
    const int* src = ei;
    const int* dst = ei + E;

    float *bufA, *bufB, *meanb, *ym9, *yr9;
    void* p;
    cudaGetSymbolAddress(&p, g_bufA);  bufA = (float*)p;
    cudaGetSymbolAddress(&p, g_bufB);  bufB = (float*)p;
    cudaGetSymbolAddress(&p, g_meanb); meanb = (float*)p;
    cudaGetSymbolAddress(&p, g_ym9);   ym9 = (float*)p;
    cudaGetSymbolAddress(&p, g_yr9);   yr9 = (float*)p;

    const int SM256 = (8192 + 2 * 256 * 32 + 3 * 256 + 1024) * 4;
    const int SMD128 = (8192 + 4 * 128 * 32 + 128) * 4;
    cudaFuncSetAttribute(k_gemm_tc<128, 256>, cudaFuncAttributeMaxDynamicSharedMemorySize, SM256);
    cudaFuncSetAttribute(k_gemm_tc<256, 256>, cudaFuncAttributeMaxDynamicSharedMemorySize, SM256);
    cudaFuncSetAttribute(k_gemm_dual<256, 128>, cudaFuncAttributeMaxDynamicSharedMemorySize, SMD128);

    // CSR build (g_deg is zeroed at module load / by previous launch's k_agg9)
    k_hist<<<(E + 255) / 256, 256>>>(dst, E);
    k_scan<<<1, 1024>>>(N);
    k_scatter<<<(E + 255) / 256, 256>>>(src, dst, E);

    int aggBlocks = (N + 7) / 8;
    int gemmBlocks = (N + 127) / 128;

    // Layer 1: 128 -> 256 (aggregate-first)
    k_agg<128><<<aggBlocks, 256>>>(z, meanb, N);
    k_gemm_tc<128, 256><<<gemmBlocks, 512, SM256>>>(meanb, z, wm1, wr1, b1, g1, be1, bufA, N);
    // Layer 2: 256 -> 256 (aggregate-first)
    k_agg<256><<<aggBlocks, 256>>>(bufA, meanb, N);
    k_gemm_tc<256, 256><<<gemmBlocks, 512, SM256>>>(meanb, bufA, wm2, wr2, b2, g2, be2, bufB, N);
    // Layer 3: 256 -> 128 (aggregate-AFTER)
    k_gemm_dual<256, 128><<<gemmBlocks, 512, SMD128>>>(bufB, wm3, wr3, b3, meanb, bufA, N);
    k_agg<128><<<aggBlocks, 256>>>(meanb, bufB, N);
    k_addlnrelu<<<aggBlocks, 256>>>(bufB, bufA, g3, be3, meanb, N);
    // Layer 4: 128 -> 9 (aggregate-AFTER)
    k_out_dual<<<aggBlocks, 256>>>(meanb, wm4, wr4, b4, ym9, yr9, N);
    k_agg9<<<aggBlocks, 256>>>(ym9, yr9, (float*)d_out, N);
}

// round 8
// speedup vs baseline: 2.0969x; 1.1797x over previous
#include <cuda_runtime.h>
#include <cstdint>

// ================= static scratch =================
#define NMAX 100352
#define EMAX 1700000

__device__ int   g_deg[NMAX];     // zeroed at load; re-zeroed by k_agg9 each launch
__device__ int   g_off[NMAX + 1];
__device__ int   g_cur[NMAX];
__device__ int   g_csr[EMAX];
__device__ float g_cnt[NMAX];
__device__ float g_bufA[(size_t)NMAX * 256];
__device__ float g_bufB[(size_t)NMAX * 256];
__device__ float g_meanb[(size_t)NMAX * 256];
__device__ float g_ym9[(size_t)NMAX * 9];
__device__ float g_yr9[(size_t)NMAX * 9];
// pre-rounded (tf32) weights
__device__ float g_wm1t[128 * 256];
__device__ float g_wr1t[128 * 256];
__device__ float g_wm2t[256 * 256];
__device__ float g_wr2t[256 * 256];
__device__ float g_wm3t[256 * 128];
__device__ float g_wr3t[256 * 128];

// ================= helpers =================
__device__ __forceinline__ uint32_t tf32r(float f) {
    uint32_t u;
    asm("cvt.rna.tf32.f32 %0, %1;" : "=r"(u) : "f"(f));
    return u;
}
__device__ __forceinline__ void mma_tf32(float* c, uint32_t a0, uint32_t a1, uint32_t a2, uint32_t a3,
                                         uint32_t b0, uint32_t b1) {
    asm volatile("mma.sync.aligned.m16n8k8.row.col.f32.tf32.tf32.f32 "
                 "{%0,%1,%2,%3}, {%4,%5,%6,%7}, {%8,%9}, {%0,%1,%2,%3};"
                 : "+f"(c[0]), "+f"(c[1]), "+f"(c[2]), "+f"(c[3])
                 : "r"(a0), "r"(a1), "r"(a2), "r"(a3), "r"(b0), "r"(b1));
}
__device__ __forceinline__ uint32_t su32(const void* p) {
    uint32_t a;
    asm("{ .reg .u64 t; cvta.to.shared.u64 t, %1; cvt.u32.u64 %0, t; }" : "=r"(a) : "l"(p));
    return a;
}
__device__ __forceinline__ void cpa16(uint32_t dst, const void* src, bool pred) {
    int sz = pred ? 16 : 0;
    asm volatile("cp.async.cg.shared.global [%0], [%1], 16, %2;" :: "r"(dst), "l"(src), "r"(sz));
}
#define CP_COMMIT() asm volatile("cp.async.commit_group;" ::: "memory")
#define CP_WAIT1()  asm volatile("cp.async.wait_group 1;" ::: "memory")
#define CP_WAIT0()  asm volatile("cp.async.wait_group 0;" ::: "memory")

// ================= CSR build =================
__global__ void k_hist(const int* __restrict__ dst, int E) {
    int e = blockIdx.x * blockDim.x + threadIdx.x;
    if (e < E) atomicAdd(&g_deg[dst[e]], 1);
}
__global__ void k_scan(int n) {
    __shared__ int part[1024];
    int t = threadIdx.x;
    int chunk = (n + 1023) / 1024;
    int beg = t * chunk;
    int end = min(beg + chunk, n);
    int s = 0;
    for (int i = beg; i < end; i++) s += g_deg[i];
    part[t] = s;
    __syncthreads();
    for (int off = 1; off < 1024; off <<= 1) {
        int v = (t >= off) ? part[t - off] : 0;
        __syncthreads();
        part[t] += v;
        __syncthreads();
    }
    int run = (t == 0) ? 0 : part[t - 1];
    for (int i = beg; i < end; i++) {
        int d = g_deg[i];
        g_off[i] = run;
        g_cur[i] = run;
        g_cnt[i] = (d > 0) ? (float)d : 1.0f;
        run += d;
    }
    if (end == n) g_off[n] = run;
}
__global__ void k_scatter(const int* __restrict__ src, const int* __restrict__ dst, int E) {
    int e = blockIdx.x * blockDim.x + threadIdx.x;
    if (e < E) {
        int p = atomicAdd(&g_cur[dst[e]], 1);
        g_csr[p] = src[e];
    }
}

// ================= weight tf32 pre-round =================
__global__ void k_tf32cvt(const float* __restrict__ src, float* __restrict__ dst, int n) {
    int i = blockIdx.x * blockDim.x + threadIdx.x;
    if (i < n) dst[i] = __uint_as_float(tf32r(src[i]));
}

// ================= mean aggregation: one warp per node (2x edge unroll) =================
template <int D>
__global__ void k_agg(const float* __restrict__ x, float* __restrict__ meanp, int n) {
    int gw = (blockIdx.x * blockDim.x + threadIdx.x) >> 5;
    int lane = threadIdx.x & 31;
    if (gw >= n) return;
    int b = g_off[gw], e = g_off[gw + 1];
    constexpr int IT = D / 128;
    float4 acc[IT], acc2[IT];
#pragma unroll
    for (int it = 0; it < IT; it++) {
        acc[it] = make_float4(0.f, 0.f, 0.f, 0.f);
        acc2[it] = make_float4(0.f, 0.f, 0.f, 0.f);
    }
    int j = b;
    for (; j + 1 < e; j += 2) {
        const float4* r0 = (const float4*)(x + (size_t)g_csr[j] * D);
        const float4* r1 = (const float4*)(x + (size_t)g_csr[j + 1] * D);
#pragma unroll
        for (int it = 0; it < IT; it++) {
            float4 v0 = r0[lane + it * 32];
            float4 v1 = r1[lane + it * 32];
            acc[it].x += v0.x; acc[it].y += v0.y; acc[it].z += v0.z; acc[it].w += v0.w;
            acc2[it].x += v1.x; acc2[it].y += v1.y; acc2[it].z += v1.z; acc2[it].w += v1.w;
        }
    }
    if (j < e) {
        const float4* r0 = (const float4*)(x + (size_t)g_csr[j] * D);
#pragma unroll
        for (int it = 0; it < IT; it++) {
            float4 v0 = r0[lane + it * 32];
            acc[it].x += v0.x; acc[it].y += v0.y; acc[it].z += v0.z; acc[it].w += v0.w;
        }
    }
    float inv = 1.0f / g_cnt[gw];
    float4* mo = (float4*)(meanp + (size_t)gw * D);
#pragma unroll
    for (int it = 0; it < IT; it++) {
        float4 v = acc[it];
        v.x = (v.x + acc2[it].x) * inv;
        v.y = (v.y + acc2[it].y) * inv;
        v.z = (v.z + acc2[it].z) * inv;
        v.w = (v.w + acc2[it].w) * inv;
        mo[lane + it * 32] = v;
    }
}

// ================= tf32 mma fused dual-GEMM + bias + LN + ReLU =================
// cp.async 3-stage pipeline, raw fp32 staging (W pre-rounded to tf32 bits),
// A pitch 36 / B pitch DOUT+8 -> conflict-free fragment LDS.32.
// 16 warps = Wm4 x Wn4, warp = 32 rows x DOUT/4 cols.
template <int DIN, int DOUT>
__launch_bounds__(512)
__global__ void k_gemm_tc(const float* __restrict__ A0, const float* __restrict__ A1,
                          const float* __restrict__ W0t, const float* __restrict__ W1t,
                          const float* __restrict__ bias, const float* __restrict__ gamma,
                          const float* __restrict__ beta, float* __restrict__ out, int n) {
    extern __shared__ float sm[];
    constexpr int NCH = DIN / 32;
    constexpr int TOT = 2 * NCH;
    constexpr int NT = DOUT / 32;
    constexpr int AP = 36;               // A row pitch (floats)
    constexpr int ASZ = 128 * AP;
    constexpr int BP = DOUT + 8;         // B row pitch
    constexpr int BSZ = 32 * BP;
    constexpr int BQ = DOUT / 4;

    float* Ab[3] = { sm, sm + ASZ, sm + 2 * ASZ };
    float* Bb[3] = { sm + 3 * ASZ, sm + 3 * ASZ + BSZ, sm + 3 * ASZ + 2 * BSZ };
    float* sp = sm + 3 * ASZ + 3 * BSZ;  // bias|gamma|beta
    float* sln = sp + 3 * DOUT;          // [128][4] float2

    int t = threadIdx.x;
    int wid = t >> 5, lane = t & 31;
    int g = lane >> 2, tq = lane & 3;
    int mw = wid & 3, nq = wid >> 2;
    int nbase = nq * (DOUT / 4);
    int row0 = blockIdx.x * 128;

    for (int i = t; i < DOUT; i += 512) {
        sp[i] = bias[i];
        sp[DOUT + i] = gamma[i];
        sp[2 * DOUT + i] = beta[i];
    }
    __syncthreads();

    float acc[2][NT][4];
#pragma unroll
    for (int ms = 0; ms < 2; ms++)
#pragma unroll
        for (int nt = 0; nt < NT; nt++)
#pragma unroll
            for (int j = 0; j < 4; j++) acc[ms][nt][j] = 0.f;

    auto copy_chunk = [&](int c, int ib) {
        const float* A = (c < NCH) ? A0 : A1;
        const float* W = (c < NCH) ? W0t : W1t;
        int k0 = ((c < NCH) ? c : c - NCH) * 32;
        uint32_t abase = su32(Ab[ib]);
        uint32_t bbase = su32(Bb[ib]);
#pragma unroll
        for (int i = 0; i < 2; i++) {         // A: 128x32 = 1024 float4
            int s = t + i * 512;
            int r = s >> 3, c4 = s & 7;
            int gr = row0 + r;
            bool ok = gr < n;
            int cr = ok ? gr : (n - 1);
            cpa16(abase + (uint32_t)(r * AP + c4 * 4) * 4,
                  A + (size_t)cr * DIN + k0 + c4 * 4, ok);
        }
#pragma unroll
        for (int i = 0; i < 32 * BQ / 512; i++) {  // B: 32 x DOUT
            int s = t + i * 512;
            int kr = s / BQ, c4 = s % BQ;
            cpa16(bbase + (uint32_t)(kr * BP + c4 * 4) * 4,
                  W + (size_t)(k0 + kr) * DOUT + c4 * 4, true);
        }
    };

    auto mma_chunk = [&](int ib) {
        const float* As = Ab[ib];
        const float* Bs = Bb[ib];
#pragma unroll
        for (int ks = 0; ks < 4; ks++) {
            int kb = ks * 8 + tq;
            uint32_t bf0[NT], bf1[NT];
#pragma unroll
            for (int nt = 0; nt < NT; nt++) {
                int nn = nbase + nt * 8 + g;
                bf0[nt] = __float_as_uint(Bs[kb * BP + nn]);
                bf1[nt] = __float_as_uint(Bs[(kb + 4) * BP + nn]);
            }
#pragma unroll
            for (int ms = 0; ms < 2; ms++) {
                int ar = mw * 32 + ms * 16 + g;
                uint32_t a0 = tf32r(As[ar * AP + kb]);
                uint32_t a1 = tf32r(As[(ar + 8) * AP + kb]);
                uint32_t a2 = tf32r(As[ar * AP + kb + 4]);
                uint32_t a3 = tf32r(As[(ar + 8) * AP + kb + 4]);
#pragma unroll
                for (int nt = 0; nt < NT; nt++)
                    mma_tf32(acc[ms][nt], a0, a1, a2, a3, bf0[nt], bf1[nt]);
            }
        }
    };

    copy_chunk(0, 0); CP_COMMIT();
    copy_chunk(1, 1); CP_COMMIT();
    for (int c = 0; c < TOT; c++) {
        if (c < TOT - 1) CP_WAIT1(); else CP_WAIT0();
        __syncthreads();
        if (c + 2 < TOT) { copy_chunk(c + 2, (c + 2) % 3); CP_COMMIT(); }
        mma_chunk(c % 3);
    }

    // ---- epilogue: +bias, LN over DOUT (4 n-quarter partials), ReLU ----
#pragma unroll
    for (int ms = 0; ms < 2; ms++) {
        float s0 = 0.f, ss0 = 0.f, s1 = 0.f, ss1 = 0.f;
#pragma unroll
        for (int nt = 0; nt < NT; nt++) {
            int col = nbase + nt * 8 + 2 * tq;
            float b0 = sp[col], b1 = sp[col + 1];
            acc[ms][nt][0] += b0; acc[ms][nt][1] += b1;
            acc[ms][nt][2] += b0; acc[ms][nt][3] += b1;
            s0 += acc[ms][nt][0] + acc[ms][nt][1];
            ss0 += acc[ms][nt][0] * acc[ms][nt][0] + acc[ms][nt][1] * acc[ms][nt][1];
            s1 += acc[ms][nt][2] + acc[ms][nt][3];
            ss1 += acc[ms][nt][2] * acc[ms][nt][2] + acc[ms][nt][3] * acc[ms][nt][3];
        }
#pragma unroll
        for (int o = 1; o <= 2; o <<= 1) {
            s0 += __shfl_xor_sync(0xffffffffu, s0, o);
            ss0 += __shfl_xor_sync(0xffffffffu, ss0, o);
            s1 += __shfl_xor_sync(0xffffffffu, s1, o);
            ss1 += __shfl_xor_sync(0xffffffffu, ss1, o);
        }
        if (tq == 0) {
            int r0 = mw * 32 + ms * 16 + g;
            ((float2*)sln)[r0 * 4 + nq] = make_float2(s0, ss0);
            ((float2*)sln)[(r0 + 8) * 4 + nq] = make_float2(s1, ss1);
        }
    }
    __syncthreads();
#pragma unroll
    for (int ms = 0; ms < 2; ms++) {
        int rl0 = mw * 32 + ms * 16 + g, rl1 = rl0 + 8;
        float s0 = 0.f, ss0 = 0.f, s1 = 0.f, ss1 = 0.f;
#pragma unroll
        for (int q = 0; q < 4; q++) {
            float2 p0 = ((float2*)sln)[rl0 * 4 + q];
            float2 p1 = ((float2*)sln)[rl1 * 4 + q];
            s0 += p0.x; ss0 += p0.y;
            s1 += p1.x; ss1 += p1.y;
        }
        float mu0 = s0 * (1.0f / DOUT);
        float rs0 = rsqrtf(ss0 * (1.0f / DOUT) - mu0 * mu0 + 1e-5f);
        float mu1 = s1 * (1.0f / DOUT);
        float rs1 = rsqrtf(ss1 * (1.0f / DOUT) - mu1 * mu1 + 1e-5f);
        int grow0 = row0 + rl0, grow1 = row0 + rl1;
#pragma unroll
        for (int nt = 0; nt < NT; nt++) {
            int col = nbase + nt * 8 + 2 * tq;
            float ga0 = sp[DOUT + col], ga1 = sp[DOUT + col + 1];
            float bt0 = sp[2 * DOUT + col], bt1 = sp[2 * DOUT + col + 1];
            if (grow0 < n) {
                float2 v;
                v.x = fmaxf((acc[ms][nt][0] - mu0) * rs0 * ga0 + bt0, 0.f);
                v.y = fmaxf((acc[ms][nt][1] - mu0) * rs0 * ga1 + bt1, 0.f);
                *(float2*)(out + (size_t)grow0 * DOUT + col) = v;
            }
            if (grow1 < n) {
                float2 v;
                v.x = fmaxf((acc[ms][nt][2] - mu1) * rs1 * ga0 + bt0, 0.f);
                v.y = fmaxf((acc[ms][nt][3] - mu1) * rs1 * ga1 + bt1, 0.f);
                *(float2*)(out + (size_t)grow1 * DOUT + col) = v;
            }
        }
    }
}

// ================= dual-output GEMM: YM = X@W0, YR = X@W1 + b =================
template <int DIN, int DOUT>
__launch_bounds__(512)
__global__ void k_gemm_dual(const float* __restrict__ X,
                            const float* __restrict__ W0t, const float* __restrict__ W1t,
                            const float* __restrict__ bias,
                            float* __restrict__ ym, float* __restrict__ yr, int n) {
    extern __shared__ float sm[];
    constexpr int NCH = DIN / 32;
    constexpr int NT = DOUT / 32;
    constexpr int AP = 36;
    constexpr int ASZ = 128 * AP;
    constexpr int BP = DOUT + 8;
    constexpr int BSZ = 32 * BP;
    constexpr int BQ = DOUT / 4;

    float* Ab[3] = { sm, sm + ASZ, sm + 2 * ASZ };
    float* B0b[3] = { sm + 3 * ASZ, sm + 3 * ASZ + BSZ, sm + 3 * ASZ + 2 * BSZ };
    float* B1b[3] = { sm + 3 * ASZ + 3 * BSZ, sm + 3 * ASZ + 4 * BSZ, sm + 3 * ASZ + 5 * BSZ };
    float* sp = sm + 3 * ASZ + 6 * BSZ;

    int t = threadIdx.x;
    int wid = t >> 5, lane = t & 31;
    int g = lane >> 2, tq = lane & 3;
    int mw = wid & 3, nq = wid >> 2;
    int nbase = nq * (DOUT / 4);
    int row0 = blockIdx.x * 128;

    for (int i = t; i < DOUT; i += 512) sp[i] = bias[i];
    __syncthreads();

    float accM[2][NT][4], accR[2][NT][4];
#pragma unroll
    for (int ms = 0; ms < 2; ms++)
#pragma unroll
        for (int nt = 0; nt < NT; nt++)
#pragma unroll
            for (int j = 0; j < 4; j++) { accM[ms][nt][j] = 0.f; accR[ms][nt][j] = 0.f; }

    auto copy_chunk = [&](int c, int ib) {
        int k0 = c * 32;
        uint32_t abase = su32(Ab[ib]);
        uint32_t b0base = su32(B0b[ib]);
        uint32_t b1base = su32(B1b[ib]);
#pragma unroll
        for (int i = 0; i < 2; i++) {
            int s = t + i * 512;
            int r = s >> 3, c4 = s & 7;
            int gr = row0 + r;
            bool ok = gr < n;
            int cr = ok ? gr : (n - 1);
            cpa16(abase + (uint32_t)(r * AP + c4 * 4) * 4,
                  X + (size_t)cr * DIN + k0 + c4 * 4, ok);
        }
#pragma unroll
        for (int i = 0; i < 32 * BQ / 512; i++) {
            int s = t + i * 512;
            int kr = s / BQ, c4 = s % BQ;
            size_t wo = (size_t)(k0 + kr) * DOUT + c4 * 4;
            uint32_t so = (uint32_t)(kr * BP + c4 * 4) * 4;
            cpa16(b0base + so, W0t + wo, true);
            cpa16(b1base + so, W1t + wo, true);
        }
    };

    auto mma_chunk = [&](int ib) {
        const float* As = Ab[ib];
        const float* B0s = B0b[ib];
        const float* B1s = B1b[ib];
#pragma unroll
        for (int ks = 0; ks < 4; ks++) {
            int kb = ks * 8 + tq;
            uint32_t bfM0[NT], bfM1[NT], bfR0[NT], bfR1[NT];
#pragma unroll
            for (int nt = 0; nt < NT; nt++) {
                int nn = nbase + nt * 8 + g;
                bfM0[nt] = __float_as_uint(B0s[kb * BP + nn]);
                bfM1[nt] = __float_as_uint(B0s[(kb + 4) * BP + nn]);
                bfR0[nt] = __float_as_uint(B1s[kb * BP + nn]);
                bfR1[nt] = __float_as_uint(B1s[(kb + 4) * BP + nn]);
            }
#pragma unroll
            for (int ms = 0; ms < 2; ms++) {
                int ar = mw * 32 + ms * 16 + g;
                uint32_t a0 = tf32r(As[ar * AP + kb]);
                uint32_t a1 = tf32r(As[(ar + 8) * AP + kb]);
                uint32_t a2 = tf32r(As[ar * AP + kb + 4]);
                uint32_t a3 = tf32r(As[(ar + 8) * AP + kb + 4]);
#pragma unroll
                for (int nt = 0; nt < NT; nt++) {
                    mma_tf32(accM[ms][nt], a0, a1, a2, a3, bfM0[nt], bfM1[nt]);
                    mma_tf32(accR[ms][nt], a0, a1, a2, a3, bfR0[nt], bfR1[nt]);
                }
            }
        }
    };

    copy_chunk(0, 0); CP_COMMIT();
    copy_chunk(1, 1); CP_COMMIT();
    for (int c = 0; c < NCH; c++) {
        if (c < NCH - 1) CP_WAIT1(); else CP_WAIT0();
        __syncthreads();
        if (c + 2 < NCH) { copy_chunk(c + 2, (c + 2) % 3); CP_COMMIT(); }
        mma_chunk(c % 3);
    }

#pragma unroll
    for (int ms = 0; ms < 2; ms++) {
        int rl0 = mw * 32 + ms * 16 + g, rl1 = rl0 + 8;
        int grow0 = row0 + rl0, grow1 = row0 + rl1;
#pragma unroll
        for (int nt = 0; nt < NT; nt++) {
            int col = nbase + nt * 8 + 2 * tq;
            float b0 = sp[col], b1 = sp[col + 1];
            if (grow0 < n) {
                *(float2*)(ym + (size_t)grow0 * DOUT + col) = make_float2(accM[ms][nt][0], accM[ms][nt][1]);
                *(float2*)(yr + (size_t)grow0 * DOUT + col) = make_float2(accR[ms][nt][0] + b0, accR[ms][nt][1] + b1);
            }
            if (grow1 < n) {
                *(float2*)(ym + (size_t)grow1 * DOUT + col) = make_float2(accM[ms][nt][2], accM[ms][nt][3]);
                *(float2*)(yr + (size_t)grow1 * DOUT + col) = make_float2(accR[ms][nt][2] + b0, accR[ms][nt][3] + b1);
            }
        }
    }
}

// ================= elementwise: out = ReLU(LN(mean + yr)), D=128, warp/row =================
__global__ void k_addlnrelu(const float* __restrict__ meanp, const float* __restrict__ yr,
                            const float* __restrict__ gamma, const float* __restrict__ beta,
                            float* __restrict__ out, int n) {
    int row = (blockIdx.x * blockDim.x + threadIdx.x) >> 5;
    int lane = threadIdx.x & 31;
    if (row >= n) return;
    float4 m4 = ((const float4*)(meanp + (size_t)row * 128))[lane];
    float4 y4 = ((const float4*)(yr + (size_t)row * 128))[lane];
    float v[4] = { m4.x + y4.x, m4.y + y4.y, m4.z + y4.z, m4.w + y4.w };
    float s = v[0] + v[1] + v[2] + v[3];
    float ss = v[0] * v[0] + v[1] * v[1] + v[2] * v[2] + v[3] * v[3];
#pragma unroll
    for (int o = 16; o; o >>= 1) {
        s += __shfl_xor_sync(0xffffffffu, s, o);
        ss += __shfl_xor_sync(0xffffffffu, ss, o);
    }
    float mu = s * (1.0f / 128.0f);
    float var = ss * (1.0f / 128.0f) - mu * mu;
    float rs = rsqrtf(var + 1e-5f);
    float4 g4 = ((const float4*)gamma)[lane];
    float4 b4 = ((const float4*)beta)[lane];
    float4 o4;
    o4.x = fmaxf((v[0] - mu) * rs * g4.x + b4.x, 0.f);
    o4.y = fmaxf((v[1] - mu) * rs * g4.y + b4.y, 0.f);
    o4.z = fmaxf((v[2] - mu) * rs * g4.z + b4.z, 0.f);
    o4.w = fmaxf((v[3] - mu) * rs * g4.w + b4.w, 0.f);
    ((float4*)(out + (size_t)row * 128))[lane] = o4;
}

// ================= final layer part 1: ym9 = x@Wm4, yr9 = x@Wr4 + b4 =================
__global__ void k_out_dual(const float* __restrict__ x,
                           const float* __restrict__ wm, const float* __restrict__ wr,
                           const float* __restrict__ bias,
                           float* __restrict__ ym9, float* __restrict__ yr9, int n) {
    __shared__ float swm[128 * 9];
    __shared__ float swr[128 * 9];
    __shared__ float sb[9];
    for (int i = threadIdx.x; i < 128 * 9; i += blockDim.x) {
        swm[i] = wm[i];
        swr[i] = wr[i];
    }
    if (threadIdx.x < 9) sb[threadIdx.x] = bias[threadIdx.x];
    __syncthreads();

    int gw = (blockIdx.x * blockDim.x + threadIdx.x) >> 5;
    int lane = threadIdx.x & 31;
    if (gw >= n) return;

    float4 ax = ((const float4*)(x + (size_t)gw * 128))[lane];
    float x4[4] = { ax.x, ax.y, ax.z, ax.w };

    float om[9], orr[9];
#pragma unroll
    for (int j = 0; j < 9; j++) { om[j] = 0.f; orr[j] = 0.f; }
#pragma unroll
    for (int q = 0; q < 4; q++) {
        int k = lane * 4 + q;
#pragma unroll
        for (int j = 0; j < 9; j++) {
            om[j] += x4[q] * swm[k * 9 + j];
            orr[j] += x4[q] * swr[k * 9 + j];
        }
    }
#pragma unroll
    for (int j = 0; j < 9; j++)
#pragma unroll
        for (int s = 16; s; s >>= 1) {
            om[j] += __shfl_xor_sync(0xffffffffu, om[j], s);
            orr[j] += __shfl_xor_sync(0xffffffffu, orr[j], s);
        }
    if (lane < 9) {
        ym9[(size_t)gw * 9 + lane] = om[lane];
        yr9[(size_t)gw * 9 + lane] = orr[lane] + sb[lane];
    }
}

// ================= final layer part 2: out = mean(ym9[src]) + yr9; re-zero g_deg =================
__global__ void k_agg9(const float* __restrict__ ym9, const float* __restrict__ yr9,
                       float* __restrict__ out, int n) {
    int gt = blockIdx.x * blockDim.x + threadIdx.x;
    if (gt < NMAX) g_deg[gt] = 0;
    int gw = gt >> 5;
    int lane = threadIdx.x & 31;
    if (gw >= n) return;
    int b = g_off[gw], e = g_off[gw + 1];
    float acc[9];
#pragma unroll
    for (int j = 0; j < 9; j++) acc[j] = 0.f;
    for (int j = b + lane; j < e; j += 32) {
        const float* row = ym9 + (size_t)g_csr[j] * 9;
#pragma unroll
        for (int c = 0; c < 9; c++) acc[c] += row[c];
    }
#pragma unroll
    for (int c = 0; c < 9; c++)
#pragma unroll
        for (int s = 16; s; s >>= 1) acc[c] += __shfl_xor_sync(0xffffffffu, acc[c], s);
    if (lane < 9) {
        float inv = 1.0f / g_cnt[gw];
        out[(size_t)gw * 9 + lane] = acc[lane] * inv + yr9[(size_t)gw * 9 + lane];
    }
}

// ================= launch =================
extern "C" void kernel_launch(void* const* d_in, const int* in_sizes, int n_in,
                              void* d_out, int out_size) {
    const float* z = (const float*)d_in[0];
    const int* ei = (const int*)d_in[1];
    const float* wm1 = (const float*)d_in[2];
    const float* wr1 = (const float*)d_in[3];
    const float* b1 = (const float*)d_in[4];
    const float* g1 = (const float*)d_in[5];
    const float* be1 = (const float*)d_in[6];
    const float* wm2 = (const float*)d_in[7];
    const float* wr2 = (const float*)d_in[8];
    const float* b2 = (const float*)d_in[9];
    const float* g2 = (const float*)d_in[10];
    const float* be2 = (const float*)d_in[11];
    const float* wm3 = (const float*)d_in[12];
    const float* wr3 = (const float*)d_in[13];
    const float* b3 = (const float*)d_in[14];
    const float* g3 = (const float*)d_in[15];
    const float* be3 = (const float*)d_in[16];
    const float* wm4 = (const float*)d_in[17];
    const float* wr4 = (const float*)d_in[18];
    const float* b4 = (const float*)d_in[19];

    int N = in_sizes[0] / 128;
    int E = in_sizes[1] / 2;
    const int* src = ei;
    const int* dst = ei + E;

    float *bufA, *bufB, *meanb, *ym9, *yr9;
    float *wm1t, *wr1t, *wm2t, *wr2t, *wm3t, *wr3t;
    void* p;
    cudaGetSymbolAddress(&p, g_bufA);  bufA = (float*)p;
    cudaGetSymbolAddress(&p, g_bufB);  bufB = (float*)p;
    cudaGetSymbolAddress(&p, g_meanb); meanb = (float*)p;
    cudaGetSymbolAddress(&p, g_ym9);   ym9 = (float*)p;
    cudaGetSymbolAddress(&p, g_yr9);   yr9 = (float*)p;
    cudaGetSymbolAddress(&p, g_wm1t);  wm1t = (float*)p;
    cudaGetSymbolAddress(&p, g_wr1t);  wr1t = (float*)p;
    cudaGetSymbolAddress(&p, g_wm2t);  wm2t = (float*)p;
    cudaGetSymbolAddress(&p, g_wr2t);  wr2t = (float*)p;
    cudaGetSymbolAddress(&p, g_wm3t);  wm3t = (float*)p;
    cudaGetSymbolAddress(&p, g_wr3t);  wr3t = (float*)p;

    // smem: gemm_tc: 3*128*36 + 3*32*(DOUT+8) + 3*DOUT + 1024 floats
    const int SM256 = (3 * 128 * 36 + 3 * 32 * 264 + 3 * 256 + 1024) * 4;
    const int SMD128 = (3 * 128 * 36 + 6 * 32 * 136 + 128) * 4;
    cudaFuncSetAttribute(k_gemm_tc<128, 256>, cudaFuncAttributeMaxDynamicSharedMemorySize, SM256);
    cudaFuncSetAttribute(k_gemm_tc<256, 256>, cudaFuncAttributeMaxDynamicSharedMemorySize, SM256);
    cudaFuncSetAttribute(k_gemm_dual<256, 128>, cudaFuncAttributeMaxDynamicSharedMemorySize, SMD128);

    // CSR build
    k_hist<<<(E + 255) / 256, 256>>>(dst, E);
    k_scan<<<1, 1024>>>(N);
    k_scatter<<<(E + 255) / 256, 256>>>(src, dst, E);

    int aggBlocks = (N + 7) / 8;
    int gemmBlocks = (N + 127) / 128;

    // Layer 1 agg (captured profile slot)
    k_agg<128><<<aggBlocks, 256>>>(z, meanb, N);

    // weight pre-round (tf32)
    k_tf32cvt<<<(128 * 256 + 255) / 256, 256>>>(wm1, wm1t, 128 * 256);
    k_tf32cvt<<<(128 * 256 + 255) / 256, 256>>>(wr1, wr1t, 128 * 256);
    k_tf32cvt<<<(256 * 256 + 255) / 256, 256>>>(wm2, wm2t, 256 * 256);
    k_tf32cvt<<<(256 * 256 + 255) / 256, 256>>>(wr2, wr2t, 256 * 256);
    k_tf32cvt<<<(256 * 128 + 255) / 256, 256>>>(wm3, wm3t, 256 * 128);
    k_tf32cvt<<<(256 * 128 + 255) / 256, 256>>>(wr3, wr3t, 256 * 128);

    // Layer 1: 128 -> 256 (aggregate-first)
    k_gemm_tc<128, 256><<<gemmBlocks, 512, SM256>>>(meanb, z, wm1t, wr1t, b1, g1, be1, bufA, N);
    // Layer 2: 256 -> 256 (aggregate-first)
    k_agg<256><<<aggBlocks, 256>>>(bufA, meanb, N);
    k_gemm_tc<256, 256><<<gemmBlocks, 512, SM256>>>(meanb, bufA, wm2t, wr2t, b2, g2, be2, bufB, N);
    // Layer 3: 256 -> 128 (aggregate-AFTER)
    k_gemm_dual<256, 128><<<gemmBlocks, 512, SMD128>>>(bufB, wm3t, wr3t, b3, meanb, bufA, N);
    k_agg<128><<<aggBlocks, 256>>>(meanb, bufB, N);
    k_addlnrelu<<<aggBlocks, 256>>>(bufB, bufA, g3, be3, meanb, N);
    // Layer 4: 128 -> 9 (aggregate-AFTER)
    k_out_dual<<<aggBlocks, 256>>>(meanb, wm4, wr4, b4, ym9, yr9, N);
    k_agg9<<<aggBlocks, 256>>>(ym9, yr9, (float*)d_out, N);
}

// round 9
// speedup vs baseline: 2.4288x; 1.1583x over previous
#include <cuda_runtime.h>
#include <cuda_fp16.h>
#include <cstdint>

// ================= static scratch =================
#define NMAX 100352
#define EMAX 1700000

__device__ int   g_deg[NMAX];     // zeroed at load; re-zeroed by k_agg9 each launch
__device__ int   g_off[NMAX + 1];
__device__ int   g_cur[NMAX];
__device__ int   g_csr[EMAX];
__device__ float g_cnt[NMAX];
__device__ float g_bufA[(size_t)NMAX * 256];
__device__ float g_bufB[(size_t)NMAX * 256];
__device__ float g_meanb[(size_t)NMAX * 256];
__device__ float g_ym9[(size_t)NMAX * 9];
__device__ float g_yr9[(size_t)NMAX * 9];
// k-paired half2 weights: Wp[k/2][N], elem = (lo=W[2k][n], hi=W[2k+1][n])
__device__ uint32_t g_w1m[64 * 256];
__device__ uint32_t g_w1r[64 * 256];
__device__ uint32_t g_w2m[128 * 256];
__device__ uint32_t g_w2r[128 * 256];
__device__ uint32_t g_w3m[128 * 128];
__device__ uint32_t g_w3r[128 * 128];

// ================= helpers =================
__device__ __forceinline__ uint32_t f2h2(float lo, float hi) {
    uint32_t r;
    asm("cvt.rn.f16x2.f32 %0, %1, %2;" : "=r"(r) : "f"(hi), "f"(lo));
    return r;
}
__device__ __forceinline__ void mma_f16(float* c, uint32_t a0, uint32_t a1, uint32_t a2, uint32_t a3,
                                        uint32_t b0, uint32_t b1) {
    asm volatile("mma.sync.aligned.m16n8k16.row.col.f32.f16.f16.f32 "
                 "{%0,%1,%2,%3}, {%4,%5,%6,%7}, {%8,%9}, {%0,%1,%2,%3};"
                 : "+f"(c[0]), "+f"(c[1]), "+f"(c[2]), "+f"(c[3])
                 : "r"(a0), "r"(a1), "r"(a2), "r"(a3), "r"(b0), "r"(b1));
}
__device__ __forceinline__ uint32_t su32(const void* p) {
    uint32_t a;
    asm("{ .reg .u64 t; cvta.to.shared.u64 t, %1; cvt.u32.u64 %0, t; }" : "=r"(a) : "l"(p));
    return a;
}
__device__ __forceinline__ void cpa16(uint32_t dst, const void* src, bool pred) {
    int sz = pred ? 16 : 0;
    asm volatile("cp.async.cg.shared.global [%0], [%1], 16, %2;" :: "r"(dst), "l"(src), "r"(sz));
}
#define CP_COMMIT() asm volatile("cp.async.commit_group;" ::: "memory")
#define CP_WAIT1()  asm volatile("cp.async.wait_group 1;" ::: "memory")
#define CP_WAIT0()  asm volatile("cp.async.wait_group 0;" ::: "memory")

// ================= CSR build =================
__global__ void k_hist(const int* __restrict__ dst, int E) {
    int e = blockIdx.x * blockDim.x + threadIdx.x;
    if (e < E) atomicAdd(&g_deg[dst[e]], 1);
}
__global__ void k_scan(int n) {
    __shared__ int part[1024];
    int t = threadIdx.x;
    int chunk = (n + 1023) / 1024;
    int beg = t * chunk;
    int end = min(beg + chunk, n);
    int s = 0;
    for (int i = beg; i < end; i++) s += g_deg[i];
    part[t] = s;
    __syncthreads();
    for (int off = 1; off < 1024; off <<= 1) {
        int v = (t >= off) ? part[t - off] : 0;
        __syncthreads();
        part[t] += v;
        __syncthreads();
    }
    int run = (t == 0) ? 0 : part[t - 1];
    for (int i = beg; i < end; i++) {
        int d = g_deg[i];
        g_off[i] = run;
        g_cur[i] = run;
        g_cnt[i] = (d > 0) ? (float)d : 1.0f;
        run += d;
    }
    if (end == n) g_off[n] = run;
}
__global__ void k_scatter(const int* __restrict__ src, const int* __restrict__ dst, int E) {
    int e = blockIdx.x * blockDim.x + threadIdx.x;
    if (e < E) {
        int p = atomicAdd(&g_cur[dst[e]], 1);
        g_csr[p] = src[e];
    }
}

// ================= weight half2 k-pair pack =================
__global__ void k_packh2(const float* __restrict__ W, uint32_t* __restrict__ Wp, int KH, int N) {
    int i = blockIdx.x * blockDim.x + threadIdx.x;
    if (i >= KH * N) return;
    int kp = i / N, n = i - kp * N;
    Wp[i] = f2h2(W[(size_t)(2 * kp) * N + n], W[(size_t)(2 * kp + 1) * N + n]);
}

// ================= mean aggregation: one warp per node (2x edge unroll) =================
template <int D>
__global__ void k_agg(const float* __restrict__ x, float* __restrict__ meanp, int n) {
    int gw = (blockIdx.x * blockDim.x + threadIdx.x) >> 5;
    int lane = threadIdx.x & 31;
    if (gw >= n) return;
    int b = g_off[gw], e = g_off[gw + 1];
    constexpr int IT = D / 128;
    float4 acc[IT], acc2[IT];
#pragma unroll
    for (int it = 0; it < IT; it++) {
        acc[it] = make_float4(0.f, 0.f, 0.f, 0.f);
        acc2[it] = make_float4(0.f, 0.f, 0.f, 0.f);
    }
    int j = b;
    for (; j + 1 < e; j += 2) {
        const float4* r0 = (const float4*)(x + (size_t)g_csr[j] * D);
        const float4* r1 = (const float4*)(x + (size_t)g_csr[j + 1] * D);
#pragma unroll
        for (int it = 0; it < IT; it++) {
            float4 v0 = r0[lane + it * 32];
            float4 v1 = r1[lane + it * 32];
            acc[it].x += v0.x; acc[it].y += v0.y; acc[it].z += v0.z; acc[it].w += v0.w;
            acc2[it].x += v1.x; acc2[it].y += v1.y; acc2[it].z += v1.z; acc2[it].w += v1.w;
        }
    }
    if (j < e) {
        const float4* r0 = (const float4*)(x + (size_t)g_csr[j] * D);
#pragma unroll
        for (int it = 0; it < IT; it++) {
            float4 v0 = r0[lane + it * 32];
            acc[it].x += v0.x; acc[it].y += v0.y; acc[it].z += v0.z; acc[it].w += v0.w;
        }
    }
    float inv = 1.0f / g_cnt[gw];
    float4* mo = (float4*)(meanp + (size_t)gw * D);
#pragma unroll
    for (int it = 0; it < IT; it++) {
        float4 v = acc[it];
        v.x = (v.x + acc2[it].x) * inv;
        v.y = (v.y + acc2[it].y) * inv;
        v.z = (v.z + acc2[it].z) * inv;
        v.w = (v.w + acc2[it].w) * inv;
        mo[lane + it * 32] = v;
    }
}

// ================= fp16 mma fused dual-GEMM + bias + LN + ReLU =================
// out[128 x DOUT] = LNReLU( A0 @ W0 + A1 @ W1 + b ).
// cp.async 3-stage pipeline. A staged fp32 (pitch 40, conflict-free float2 frag
// loads + cvt->f16x2); W pre-packed half2 k-pairs (pitch DOUT+8 half2).
// m16n8k16.f16: half the mma count / B traffic of the tf32 k8 version,
// identical mantissa width (10 bits).
template <int DIN, int DOUT>
__launch_bounds__(512)
__global__ void k_gemm_tc(const float* __restrict__ A0, const float* __restrict__ A1,
                          const uint32_t* __restrict__ W0p, const uint32_t* __restrict__ W1p,
                          const float* __restrict__ bias, const float* __restrict__ gamma,
                          const float* __restrict__ beta, float* __restrict__ out, int n) {
    extern __shared__ float sm[];
    constexpr int NCH = DIN / 32;
    constexpr int TOT = 2 * NCH;
    constexpr int NT = DOUT / 32;
    constexpr int AP = 40;                // A row pitch (floats)
    constexpr int ASZ = 128 * AP;
    constexpr int BPH = DOUT + 8;         // B row pitch (half2 words)
    constexpr int BSZ = 16 * BPH;         // words per B stage

    float* Ab[3] = { sm, sm + ASZ, sm + 2 * ASZ };
    uint32_t* Bb[3] = { (uint32_t*)(sm + 3 * ASZ), (uint32_t*)(sm + 3 * ASZ + BSZ),
                        (uint32_t*)(sm + 3 * ASZ + 2 * BSZ) };
    float* sp = sm + 3 * ASZ + 3 * BSZ;   // bias|gamma|beta
    float* sln = sp + 3 * DOUT;           // [128][4] float2

    int t = threadIdx.x;
    int wid = t >> 5, lane = t & 31;
    int g = lane >> 2, tq = lane & 3;
    int mw = wid & 3, nq = wid >> 2;
    int nbase = nq * (DOUT / 4);
    int row0 = blockIdx.x * 128;

    for (int i = t; i < DOUT; i += 512) {
        sp[i] = bias[i];
        sp[DOUT + i] = gamma[i];
        sp[2 * DOUT + i] = beta[i];
    }
    __syncthreads();

    float acc[2][NT][4];
#pragma unroll
    for (int ms = 0; ms < 2; ms++)
#pragma unroll
        for (int nt = 0; nt < NT; nt++)
#pragma unroll
            for (int j = 0; j < 4; j++) acc[ms][nt][j] = 0.f;

    auto copy_chunk = [&](int c, int ib) {
        const float* A = (c < NCH) ? A0 : A1;
        const uint32_t* W = (c < NCH) ? W0p : W1p;
        int cc = (c < NCH) ? c : c - NCH;
        int k0 = cc * 32;        // fp32 k base
        int kph = cc * 16;       // half2 row base
        uint32_t abase = su32(Ab[ib]);
        uint32_t bbase = su32(Bb[ib]);
#pragma unroll
        for (int i = 0; i < 2; i++) {          // A: 128 x 32 fp32 = 1024 float4
            int s = t + i * 512;
            int r = s >> 3, c4 = s & 7;
            int gr = row0 + r;
            bool ok = gr < n;
            int cr = ok ? gr : (n - 1);
            cpa16(abase + (uint32_t)(r * AP + c4 * 4) * 4,
                  A + (size_t)cr * DIN + k0 + c4 * 4, ok);
        }
#pragma unroll
        for (int i = 0; i < DOUT / 128; i++) { // B: 16 rows x DOUT half2
            int s = t + i * 512;
            int kr = s / (DOUT / 4), c4 = s % (DOUT / 4);
            cpa16(bbase + (uint32_t)(kr * BPH + c4 * 4) * 4,
                  W + (size_t)(kph + kr) * DOUT + c4 * 4, true);
        }
    };

    auto mma_chunk = [&](int ib) {
        const float* As = Ab[ib];
        const uint32_t* Bs = Bb[ib];
#pragma unroll
        for (int ks = 0; ks < 2; ks++) {
            int kb = ks * 16;    // fp32 col base
            int kpb = ks * 8;    // half2 row base
            uint32_t bf0[NT], bf1[NT];
#pragma unroll
            for (int nt = 0; nt < NT; nt++) {
                int nn = nbase + nt * 8 + g;
                bf0[nt] = Bs[(kpb + tq) * BPH + nn];
                bf1[nt] = Bs[(kpb + tq + 4) * BPH + nn];
            }
#pragma unroll
            for (int ms = 0; ms < 2; ms++) {
                int ar = mw * 32 + ms * 16 + g;
                float2 v0 = *(const float2*)&As[ar * AP + kb + 2 * tq];
                float2 v1 = *(const float2*)&As[(ar + 8) * AP + kb + 2 * tq];
                float2 v2 = *(const float2*)&As[ar * AP + kb + 2 * tq + 8];
                float2 v3 = *(const float2*)&As[(ar + 8) * AP + kb + 2 * tq + 8];
                uint32_t a0 = f2h2(v0.x, v0.y);
                uint32_t a1 = f2h2(v1.x, v1.y);
                uint32_t a2 = f2h2(v2.x, v2.y);
                uint32_t a3 = f2h2(v3.x, v3.y);
#pragma unroll
                for (int nt = 0; nt < NT; nt++)
                    mma_f16(acc[ms][nt], a0, a1, a2, a3, bf0[nt], bf1[nt]);
            }
        }
    };

    copy_chunk(0, 0); CP_COMMIT();
    copy_chunk(1, 1); CP_COMMIT();
    for (int c = 0; c < TOT; c++) {
        if (c < TOT - 1) CP_WAIT1(); else CP_WAIT0();
        __syncthreads();
        if (c + 2 < TOT) { copy_chunk(c + 2, (c + 2) % 3); CP_COMMIT(); }
        mma_chunk(c % 3);
    }

    // ---- epilogue: +bias, LN over DOUT (4 n-quarter partials), ReLU ----
#pragma unroll
    for (int ms = 0; ms < 2; ms++) {
        float s0 = 0.f, ss0 = 0.f, s1 = 0.f, ss1 = 0.f;
#pragma unroll
        for (int nt = 0; nt < NT; nt++) {
            int col = nbase + nt * 8 + 2 * tq;
            float b0 = sp[col], b1 = sp[col + 1];
            acc[ms][nt][0] += b0; acc[ms][nt][1] += b1;
            acc[ms][nt][2] += b0; acc[ms][nt][3] += b1;
            s0 += acc[ms][nt][0] + acc[ms][nt][1];
            ss0 += acc[ms][nt][0] * acc[ms][nt][0] + acc[ms][nt][1] * acc[ms][nt][1];
            s1 += acc[ms][nt][2] + acc[ms][nt][3];
            ss1 += acc[ms][nt][2] * acc[ms][nt][2] + acc[ms][nt][3] * acc[ms][nt][3];
        }
#pragma unroll
        for (int o = 1; o <= 2; o <<= 1) {
            s0 += __shfl_xor_sync(0xffffffffu, s0, o);
            ss0 += __shfl_xor_sync(0xffffffffu, ss0, o);
            s1 += __shfl_xor_sync(0xffffffffu, s1, o);
            ss1 += __shfl_xor_sync(0xffffffffu, ss1, o);
        }
        if (tq == 0) {
            int r0 = mw * 32 + ms * 16 + g;
            ((float2*)sln)[r0 * 4 + nq] = make_float2(s0, ss0);
            ((float2*)sln)[(r0 + 8) * 4 + nq] = make_float2(s1, ss1);
        }
    }
    __syncthreads();
#pragma unroll
    for (int ms = 0; ms < 2; ms++) {
        int rl0 = mw * 32 + ms * 16 + g, rl1 = rl0 + 8;
        float s0 = 0.f, ss0 = 0.f, s1 = 0.f, ss1 = 0.f;
#pragma unroll
        for (int q = 0; q < 4; q++) {
            float2 p0 = ((float2*)sln)[rl0 * 4 + q];
            float2 p1 = ((float2*)sln)[rl1 * 4 + q];
            s0 += p0.x; ss0 += p0.y;
            s1 += p1.x; ss1 += p1.y;
        }
        float mu0 = s0 * (1.0f / DOUT);
        float rs0 = rsqrtf(ss0 * (1.0f / DOUT) - mu0 * mu0 + 1e-5f);
        float mu1 = s1 * (1.0f / DOUT);
        float rs1 = rsqrtf(ss1 * (1.0f / DOUT) - mu1 * mu1 + 1e-5f);
        int grow0 = row0 + rl0, grow1 = row0 + rl1;
#pragma unroll
        for (int nt = 0; nt < NT; nt++) {
            int col = nbase + nt * 8 + 2 * tq;
            float ga0 = sp[DOUT + col], ga1 = sp[DOUT + col + 1];
            float bt0 = sp[2 * DOUT + col], bt1 = sp[2 * DOUT + col + 1];
            if (grow0 < n) {
                float2 v;
                v.x = fmaxf((acc[ms][nt][0] - mu0) * rs0 * ga0 + bt0, 0.f);
                v.y = fmaxf((acc[ms][nt][1] - mu0) * rs0 * ga1 + bt1, 0.f);
                *(float2*)(out + (size_t)grow0 * DOUT + col) = v;
            }
            if (grow1 < n) {
                float2 v;
                v.x = fmaxf((acc[ms][nt][2] - mu1) * rs1 * ga0 + bt0, 0.f);
                v.y = fmaxf((acc[ms][nt][3] - mu1) * rs1 * ga1 + bt1, 0.f);
                *(float2*)(out + (size_t)grow1 * DOUT + col) = v;
            }
        }
    }
}

// ================= dual-output GEMM: YM = X@W0, YR = X@W1 + b =================
template <int DIN, int DOUT>
__launch_bounds__(512)
__global__ void k_gemm_dual(const float* __restrict__ X,
                            const uint32_t* __restrict__ W0p, const uint32_t* __restrict__ W1p,
                            const float* __restrict__ bias,
                            float* __restrict__ ym, float* __restrict__ yr, int n) {
    extern __shared__ float sm[];
    constexpr int NCH = DIN / 32;
    constexpr int NT = DOUT / 32;
    constexpr int AP = 40;
    constexpr int ASZ = 128 * AP;
    constexpr int BPH = DOUT + 8;
    constexpr int BSZ = 16 * BPH;

    float* Ab[3] = { sm, sm + ASZ, sm + 2 * ASZ };
    uint32_t* B0b[3] = { (uint32_t*)(sm + 3 * ASZ), (uint32_t*)(sm + 3 * ASZ + BSZ),
                         (uint32_t*)(sm + 3 * ASZ + 2 * BSZ) };
    uint32_t* B1b[3] = { (uint32_t*)(sm + 3 * ASZ + 3 * BSZ), (uint32_t*)(sm + 3 * ASZ + 4 * BSZ),
                         (uint32_t*)(sm + 3 * ASZ + 5 * BSZ) };
    float* sp = sm + 3 * ASZ + 6 * BSZ;

    int t = threadIdx.x;
    int wid = t >> 5, lane = t & 31;
    int g = lane >> 2, tq = lane & 3;
    int mw = wid & 3, nq = wid >> 2;
    int nbase = nq * (DOUT / 4);
    int row0 = blockIdx.x * 128;

    for (int i = t; i < DOUT; i += 512) sp[i] = bias[i];
    __syncthreads();

    float accM[2][NT][4], accR[2][NT][4];
#pragma unroll
    for (int ms = 0; ms < 2; ms++)
#pragma unroll
        for (int nt = 0; nt < NT; nt++)
#pragma unroll
            for (int j = 0; j < 4; j++) { accM[ms][nt][j] = 0.f; accR[ms][nt][j] = 0.f; }

    auto copy_chunk = [&](int c, int ib) {
        int k0 = c * 32;
        int kph = c * 16;
        uint32_t abase = su32(Ab[ib]);
        uint32_t b0base = su32(B0b[ib]);
        uint32_t b1base = su32(B1b[ib]);
#pragma unroll
        for (int i = 0; i < 2; i++) {
            int s = t + i * 512;
            int r = s >> 3, c4 = s & 7;
            int gr = row0 + r;
            bool ok = gr < n;
            int cr = ok ? gr : (n - 1);
            cpa16(abase + (uint32_t)(r * AP + c4 * 4) * 4,
                  X + (size_t)cr * DIN + k0 + c4 * 4, ok);
        }
        {   // B: 16 rows x DOUT(=128) half2, one cp per thread per array
            int kr = t / (DOUT / 4), c4 = t % (DOUT / 4);
            size_t wo = (size_t)(kph + kr) * DOUT + c4 * 4;
            uint32_t so = (uint32_t)(kr * BPH + c4 * 4) * 4;
            cpa16(b0base + so, W0p + wo, true);
            cpa16(b1base + so, W1p + wo, true);
        }
    };

    auto mma_chunk = [&](int ib) {
        const float* As = Ab[ib];
        const uint32_t* B0s = B0b[ib];
        const uint32_t* B1s = B1b[ib];
#pragma unroll
        for (int ks = 0; ks < 2; ks++) {
            int kb = ks * 16;
            int kpb = ks * 8;
            uint32_t bfM0[NT], bfM1[NT], bfR0[NT], bfR1[NT];
#pragma unroll
            for (int nt = 0; nt < NT; nt++) {
                int nn = nbase + nt * 8 + g;
                bfM0[nt] = B0s[(kpb + tq) * BPH + nn];
                bfM1[nt] = B0s[(kpb + tq + 4) * BPH + nn];
                bfR0[nt] = B1s[(kpb + tq) * BPH + nn];
                bfR1[nt] = B1s[(kpb + tq + 4) * BPH + nn];
            }
#pragma unroll
            for (int ms = 0; ms < 2; ms++) {
                int ar = mw * 32 + ms * 16 + g;
                float2 v0 = *(const float2*)&As[ar * AP + kb + 2 * tq];
                float2 v1 = *(const float2*)&As[(ar + 8) * AP + kb + 2 * tq];
                float2 v2 = *(const float2*)&As[ar * AP + kb + 2 * tq + 8];
                float2 v3 = *(const float2*)&As[(ar + 8) * AP + kb + 2 * tq + 8];
                uint32_t a0 = f2h2(v0.x, v0.y);
                uint32_t a1 = f2h2(v1.x, v1.y);
                uint32_t a2 = f2h2(v2.x, v2.y);
                uint32_t a3 = f2h2(v3.x, v3.y);
#pragma unroll
                for (int nt = 0; nt < NT; nt++) {
                    mma_f16(accM[ms][nt], a0, a1, a2, a3, bfM0[nt], bfM1[nt]);
                    mma_f16(accR[ms][nt], a0, a1, a2, a3, bfR0[nt], bfR1[nt]);
                }
            }
        }
    };

    copy_chunk(0, 0); CP_COMMIT();
    copy_chunk(1, 1); CP_COMMIT();
    for (int c = 0; c < NCH; c++) {
        if (c < NCH - 1) CP_WAIT1(); else CP_WAIT0();
        __syncthreads();
        if (c + 2 < NCH) { copy_chunk(c + 2, (c + 2) % 3); CP_COMMIT(); }
        mma_chunk(c % 3);
    }

#pragma unroll
    for (int ms = 0; ms < 2; ms++) {
        int rl0 = mw * 32 + ms * 16 + g, rl1 = rl0 + 8;
        int grow0 = row0 + rl0, grow1 = row0 + rl1;
#pragma unroll
        for (int nt = 0; nt < NT; nt++) {
            int col = nbase + nt * 8 + 2 * tq;
            float b0 = sp[col], b1 = sp[col + 1];
            if (grow0 < n) {
                *(float2*)(ym + (size_t)grow0 * DOUT + col) = make_float2(accM[ms][nt][0], accM[ms][nt][1]);
                *(float2*)(yr + (size_t)grow0 * DOUT + col) = make_float2(accR[ms][nt][0] + b0, accR[ms][nt][1] + b1);
            }
            if (grow1 < n) {
                *(float2*)(ym + (size_t)grow1 * DOUT + col) = make_float2(accM[ms][nt][2], accM[ms][nt][3]);
                *(float2*)(yr + (size_t)grow1 * DOUT + col) = make_float2(accR[ms][nt][2] + b0, accR[ms][nt][3] + b1);
            }
        }
    }
}

// ================= elementwise: out = ReLU(LN(mean + yr)), D=128, warp/row =================
__global__ void k_addlnrelu(const float* __restrict__ meanp, const float* __restrict__ yr,
                            const float* __restrict__ gamma, const float* __restrict__ beta,
                            float* __restrict__ out, int n) {
    int row = (blockIdx.x * blockDim.x + threadIdx.x) >> 5;
    int lane = threadIdx.x & 31;
    if (row >= n) return;
    float4 m4 = ((const float4*)(meanp + (size_t)row * 128))[lane];
    float4 y4 = ((const float4*)(yr + (size_t)row * 128))[lane];
    float v[4] = { m4.x + y4.x, m4.y + y4.y, m4.z + y4.z, m4.w + y4.w };
    float s = v[0] + v[1] + v[2] + v[3];
    float ss = v[0] * v[0] + v[1] * v[1] + v[2] * v[2] + v[3] * v[3];
#pragma unroll
    for (int o = 16; o; o >>= 1) {
        s += __shfl_xor_sync(0xffffffffu, s, o);
        ss += __shfl_xor_sync(0xffffffffu, ss, o);
    }
    float mu = s * (1.0f / 128.0f);
    float var = ss * (1.0f / 128.0f) - mu * mu;
    float rs = rsqrtf(var + 1e-5f);
    float4 g4 = ((const float4*)gamma)[lane];
    float4 b4 = ((const float4*)beta)[lane];
    float4 o4;
    o4.x = fmaxf((v[0] - mu) * rs * g4.x + b4.x, 0.f);
    o4.y = fmaxf((v[1] - mu) * rs * g4.y + b4.y, 0.f);
    o4.z = fmaxf((v[2] - mu) * rs * g4.z + b4.z, 0.f);
    o4.w = fmaxf((v[3] - mu) * rs * g4.w + b4.w, 0.f);
    ((float4*)(out + (size_t)row * 128))[lane] = o4;
}

// ================= final layer part 1: ym9 = x@Wm4, yr9 = x@Wr4 + b4 =================
__global__ void k_out_dual(const float* __restrict__ x,
                           const float* __restrict__ wm, const float* __restrict__ wr,
                           const float* __restrict__ bias,
                           float* __restrict__ ym9, float* __restrict__ yr9, int n) {
    __shared__ float swm[128 * 9];
    __shared__ float swr[128 * 9];
    __shared__ float sb[9];
    for (int i = threadIdx.x; i < 128 * 9; i += blockDim.x) {
        swm[i] = wm[i];
        swr[i] = wr[i];
    }
    if (threadIdx.x < 9) sb[threadIdx.x] = bias[threadIdx.x];
    __syncthreads();

    int gw = (blockIdx.x * blockDim.x + threadIdx.x) >> 5;
    int lane = threadIdx.x & 31;
    if (gw >= n) return;

    float4 ax = ((const float4*)(x + (size_t)gw * 128))[lane];
    float x4[4] = { ax.x, ax.y, ax.z, ax.w };

    float om[9], orr[9];
#pragma unroll
    for (int j = 0; j < 9; j++) { om[j] = 0.f; orr[j] = 0.f; }
#pragma unroll
    for (int q = 0; q < 4; q++) {
        int k = lane * 4 + q;
#pragma unroll
        for (int j = 0; j < 9; j++) {
            om[j] += x4[q] * swm[k * 9 + j];
            orr[j] += x4[q] * swr[k * 9 + j];
        }
    }
#pragma unroll
    for (int j = 0; j < 9; j++)
#pragma unroll
        for (int s = 16; s; s >>= 1) {
            om[j] += __shfl_xor_sync(0xffffffffu, om[j], s);
            orr[j] += __shfl_xor_sync(0xffffffffu, orr[j], s);
        }
    if (lane < 9) {
        ym9[(size_t)gw * 9 + lane] = om[lane];
        yr9[(size_t)gw * 9 + lane] = orr[lane] + sb[lane];
    }
}

// ================= final layer part 2: out = mean(ym9[src]) + yr9; re-zero g_deg =================
__global__ void k_agg9(const float* __restrict__ ym9, const float* __restrict__ yr9,
                       float* __restrict__ out, int n) {
    int gt = blockIdx.x * blockDim.x + threadIdx.x;
    if (gt < NMAX) g_deg[gt] = 0;
    int gw = gt >> 5;
    int lane = threadIdx.x & 31;
    if (gw >= n) return;
    int b = g_off[gw], e = g_off[gw + 1];
    float acc[9];
#pragma unroll
    for (int j = 0; j < 9; j++) acc[j] = 0.f;
    for (int j = b + lane; j < e; j += 32) {
        const float* row = ym9 + (size_t)g_csr[j] * 9;
#pragma unroll
        for (int c = 0; c < 9; c++) acc[c] += row[c];
    }
#pragma unroll
    for (int c = 0; c < 9; c++)
#pragma unroll
        for (int s = 16; s; s >>= 1) acc[c] += __shfl_xor_sync(0xffffffffu, acc[c], s);
    if (lane < 9) {
        float inv = 1.0f / g_cnt[gw];
        out[(size_t)gw * 9 + lane] = acc[lane] * inv + yr9[(size_t)gw * 9 + lane];
    }
}

// ================= launch =================
extern "C" void kernel_launch(void* const* d_in, const int* in_sizes, int n_in,
                              void* d_out, int out_size) {
    const float* z = (const float*)d_in[0];
    const int* ei = (const int*)d_in[1];
    const float* wm1 = (const float*)d_in[2];
    const float* wr1 = (const float*)d_in[3];
    const float* b1 = (const float*)d_in[4];
    const float* g1 = (const float*)d_in[5];
    const float* be1 = (const float*)d_in[6];
    const float* wm2 = (const float*)d_in[7];
    const float* wr2 = (const float*)d_in[8];
    const float* b2 = (const float*)d_in[9];
    const float* g2 = (const float*)d_in[10];
    const float* be2 = (const float*)d_in[11];
    const float* wm3 = (const float*)d_in[12];
    const float* wr3 = (const float*)d_in[13];
    const float* b3 = (const float*)d_in[14];
    const float* g3 = (const float*)d_in[15];
    const float* be3 = (const float*)d_in[16];
    const float* wm4 = (const float*)d_in[17];
    const float* wr4 = (const float*)d_in[18];
    const float* b4 = (const float*)d_in[19];

    int N = in_sizes[0] / 128;
    int E = in_sizes[1] / 2;
    const int* src = ei;
    const int* dst = ei + E;

    float *bufA, *bufB, *meanb, *ym9, *yr9;
    uint32_t *w1m, *w1r, *w2m, *w2r, *w3m, *w3r;
    void* p;
    cudaGetSymbolAddress(&p, g_bufA);  bufA = (float*)p;
    cudaGetSymbolAddress(&p, g_bufB);  bufB = (float*)p;
    cudaGetSymbolAddress(&p, g_meanb); meanb = (float*)p;
    cudaGetSymbolAddress(&p, g_ym9);   ym9 = (float*)p;
    cudaGetSymbolAddress(&p, g_yr9);   yr9 = (float*)p;
    cudaGetSymbolAddress(&p, g_w1m);   w1m = (uint32_t*)p;
    cudaGetSymbolAddress(&p, g_w1r);   w1r = (uint32_t*)p;
    cudaGetSymbolAddress(&p, g_w2m);   w2m = (uint32_t*)p;
    cudaGetSymbolAddress(&p, g_w2r);   w2r = (uint32_t*)p;
    cudaGetSymbolAddress(&p, g_w3m);   w3m = (uint32_t*)p;
    cudaGetSymbolAddress(&p, g_w3r);   w3r = (uint32_t*)p;

    // smem (4-byte words): gemm: 3*128*40 + 3*16*(DOUT+8) + 3*DOUT + 1024
    const int SM256 = (3 * 128 * 40 + 3 * 16 * 264 + 3 * 256 + 1024) * 4;
    const int SMD128 = (3 * 128 * 40 + 6 * 16 * 136 + 128) * 4;
    cudaFuncSetAttribute(k_gemm_tc<128, 256>, cudaFuncAttributeMaxDynamicSharedMemorySize, SM256);
    cudaFuncSetAttribute(k_gemm_tc<256, 256>, cudaFuncAttributeMaxDynamicSharedMemorySize, SM256);
    cudaFuncSetAttribute(k_gemm_dual<256, 128>, cudaFuncAttributeMaxDynamicSharedMemorySize, SMD128);

    // CSR build
    k_hist<<<(E + 255) / 256, 256>>>(dst, E);
    k_scan<<<1, 1024>>>(N);
    k_scatter<<<(E + 255) / 256, 256>>>(src, dst, E);

    int aggBlocks = (N + 7) / 8;
    int gemmBlocks = (N + 127) / 128;

    // Layer 1 agg
    k_agg<128><<<aggBlocks, 256>>>(z, meanb, N);

    // weight pack (half2 k-pairs)
    k_packh2<<<(64 * 256 + 255) / 256, 256>>>(wm1, w1m, 64, 256);
    k_packh2<<<(64 * 256 + 255) / 256, 256>>>(wr1, w1r, 64, 256);
    k_packh2<<<(128 * 256 + 255) / 256, 256>>>(wm2, w2m, 128, 256);
    k_packh2<<<(128 * 256 + 255) / 256, 256>>>(wr2, w2r, 128, 256);
    k_packh2<<<(128 * 128 + 255) / 256, 256>>>(wm3, w3m, 128, 128);
    k_packh2<<<(128 * 128 + 255) / 256, 256>>>(wr3, w3r, 128, 128);

    // Layer 1: 128 -> 256 (aggregate-first)
    k_gemm_tc<128, 256><<<gemmBlocks, 512, SM256>>>(meanb, z, w1m, w1r, b1, g1, be1, bufA, N);
    // Layer 2: 256 -> 256 (aggregate-first)
    k_agg<256><<<aggBlocks, 256>>>(bufA, meanb, N);
    k_gemm_tc<256, 256><<<gemmBlocks, 512, SM256>>>(meanb, bufA, w2m, w2r, b2, g2, be2, bufB, N);
    // Layer 3: 256 -> 128 (aggregate-AFTER)
    k_gemm_dual<256, 128><<<gemmBlocks, 512, SMD128>>>(bufB, w3m, w3r, b3, meanb, bufA, N);
    k_agg<128><<<aggBlocks, 256>>>(meanb, bufB, N);
    k_addlnrelu<<<aggBlocks, 256>>>(bufB, bufA, g3, be3, meanb, N);
    // Layer 4: 128 -> 9 (aggregate-AFTER)
    k_out_dual<<<aggBlocks, 256>>>(meanb, wm4, wr4, b4, ym9, yr9, N);
    k_agg9<<<aggBlocks, 256>>>(ym9, yr9, (float*)d_out, N);
}

// round 10
// speedup vs baseline: 2.7089x; 1.1153x over previous
#include <cuda_runtime.h>
#include <cuda_fp16.h>
#include <cstdint>

// ================= static scratch =================
#define NMAX 100352
#define EMAX 1700000

__device__ int   g_deg[NMAX];     // zeroed at load; re-zeroed by k_agg9 each launch
__device__ int   g_off[NMAX + 1];
__device__ int   g_cur[NMAX];
__device__ int   g_csr[EMAX];
__device__ float g_cnt[NMAX];
__device__ float g_ym9[(size_t)NMAX * 9];
__device__ float g_yr9[(size_t)NMAX * 9];
// fp16 activations / means
__device__ __align__(16) __half g_hz[(size_t)NMAX * 128];
__device__ __align__(16) __half g_hA[(size_t)NMAX * 256];
__device__ __align__(16) __half g_hB[(size_t)NMAX * 256];
__device__ __align__(16) __half g_hM[(size_t)NMAX * 256];
// k-paired half2 weights: Wp[k/2][N], elem = (lo=W[2k][n], hi=W[2k+1][n])
__device__ uint32_t g_w1m[64 * 256];
__device__ uint32_t g_w1r[64 * 256];
__device__ uint32_t g_w2m[128 * 256];
__device__ uint32_t g_w2r[128 * 256];
__device__ uint32_t g_w3m[128 * 128];
__device__ uint32_t g_w3r[128 * 128];

// ================= helpers =================
__device__ __forceinline__ uint32_t f2h2(float lo, float hi) {
    uint32_t r;
    asm("cvt.rn.f16x2.f32 %0, %1, %2;" : "=r"(r) : "f"(hi), "f"(lo));
    return r;
}
__device__ __forceinline__ void mma_f16(float* c, uint32_t a0, uint32_t a1, uint32_t a2, uint32_t a3,
                                        uint32_t b0, uint32_t b1) {
    asm volatile("mma.sync.aligned.m16n8k16.row.col.f32.f16.f16.f32 "
                 "{%0,%1,%2,%3}, {%4,%5,%6,%7}, {%8,%9}, {%0,%1,%2,%3};"
                 : "+f"(c[0]), "+f"(c[1]), "+f"(c[2]), "+f"(c[3])
                 : "r"(a0), "r"(a1), "r"(a2), "r"(a3), "r"(b0), "r"(b1));
}
__device__ __forceinline__ uint32_t su32(const void* p) {
    uint32_t a;
    asm("{ .reg .u64 t; cvta.to.shared.u64 t, %1; cvt.u32.u64 %0, t; }" : "=r"(a) : "l"(p));
    return a;
}
__device__ __forceinline__ void cpa16(uint32_t dst, const void* src, bool pred) {
    int sz = pred ? 16 : 0;
    asm volatile("cp.async.cg.shared.global [%0], [%1], 16, %2;" :: "r"(dst), "l"(src), "r"(sz));
}
#define CP_COMMIT() asm volatile("cp.async.commit_group;" ::: "memory")
#define CP_WAIT1()  asm volatile("cp.async.wait_group 1;" ::: "memory")
#define CP_WAIT0()  asm volatile("cp.async.wait_group 0;" ::: "memory")

// ================= CSR build =================
__global__ void k_hist(const int* __restrict__ dst, int E) {
    int e = blockIdx.x * blockDim.x + threadIdx.x;
    if (e < E) atomicAdd(&g_deg[dst[e]], 1);
}
__global__ void k_scan(int n) {
    __shared__ int part[1024];
    int t = threadIdx.x;
    int chunk = (n + 1023) / 1024;
    int beg = t * chunk;
    int end = min(beg + chunk, n);
    int s = 0;
    for (int i = beg; i < end; i++) s += g_deg[i];
    part[t] = s;
    __syncthreads();
    for (int off = 1; off < 1024; off <<= 1) {
        int v = (t >= off) ? part[t - off] : 0;
        __syncthreads();
        part[t] += v;
        __syncthreads();
    }
    int run = (t == 0) ? 0 : part[t - 1];
    for (int i = beg; i < end; i++) {
        int d = g_deg[i];
        g_off[i] = run;
        g_cur[i] = run;
        g_cnt[i] = (d > 0) ? (float)d : 1.0f;
        run += d;
    }
    if (end == n) g_off[n] = run;
}
__global__ void k_scatter(const int* __restrict__ src, const int* __restrict__ dst, int E) {
    int e = blockIdx.x * blockDim.x + threadIdx.x;
    if (e < E) {
        int p = atomicAdd(&g_cur[dst[e]], 1);
        g_csr[p] = src[e];
    }
}

// ================= conversions / packing =================
__global__ void k_z2h(const float* __restrict__ z, __half* __restrict__ zh, int n2) {
    int i = blockIdx.x * blockDim.x + threadIdx.x;
    if (i >= n2) return;
    float2 v = ((const float2*)z)[i];
    ((__half2*)zh)[i] = __floats2half2_rn(v.x, v.y);
}
__global__ void k_packh2(const float* __restrict__ W, uint32_t* __restrict__ Wp, int KH, int N) {
    int i = blockIdx.x * blockDim.x + threadIdx.x;
    if (i >= KH * N) return;
    int kp = i / N, n = i - kp * N;
    Wp[i] = f2h2(W[(size_t)(2 * kp) * N + n], W[(size_t)(2 * kp + 1) * N + n]);
}

// ================= mean aggregation (half in/out, fp32 acc) =================
template <int D>
__global__ void k_aggh(const __half* __restrict__ x, __half* __restrict__ meanp, int n) {
    int gw = (blockIdx.x * blockDim.x + threadIdx.x) >> 5;
    int lane = threadIdx.x & 31;
    if (gw >= n) return;
    int b = g_off[gw], e = g_off[gw + 1];
    constexpr int NH2 = D / 64;   // half2 per lane: 2 (D=128) or 4 (D=256)
    float2 acc[NH2], acc2[NH2];
#pragma unroll
    for (int h = 0; h < NH2; h++) {
        acc[h] = make_float2(0.f, 0.f);
        acc2[h] = make_float2(0.f, 0.f);
    }
    auto addrow = [&](const __half* rp, float2* a) {
        uint32_t w[NH2];
        if (NH2 == 4) {
            uint4 u = ((const uint4*)rp)[lane];
            w[0] = u.x; w[1] = u.y; w[2] = u.z; w[3] = u.w;
        } else {
            uint2 u = ((const uint2*)rp)[lane];
            w[0] = u.x; w[1] = u.y;
        }
#pragma unroll
        for (int h = 0; h < NH2; h++) {
            float2 f = __half22float2(*(__half2*)&w[h]);
            a[h].x += f.x;
            a[h].y += f.y;
        }
    };
    int j = b;
    for (; j + 1 < e; j += 2) {
        addrow(x + (size_t)g_csr[j] * D, acc);
        addrow(x + (size_t)g_csr[j + 1] * D, acc2);
    }
    if (j < e) addrow(x + (size_t)g_csr[j] * D, acc);

    float inv = 1.0f / g_cnt[gw];
    uint32_t o[NH2];
#pragma unroll
    for (int h = 0; h < NH2; h++) {
        __half2 hv = __floats2half2_rn((acc[h].x + acc2[h].x) * inv, (acc[h].y + acc2[h].y) * inv);
        o[h] = *(uint32_t*)&hv;
    }
    __half* mo = meanp + (size_t)gw * D;
    if (NH2 == 4) ((uint4*)mo)[lane] = make_uint4(o[0], o[1], o[2], o[3]);
    else ((uint2*)mo)[lane] = make_uint2(o[0], o[1]);
}

// ================= fp16 mma fused dual-GEMM + bias + LN + ReLU =================
// out[128 x DOUT] = LNReLU( A0 @ W0 + A1 @ W1 + b ). All activations fp16.
// A staged as halves (pitch 40 halves = 80B; fragments = single LDS.32, no cvt,
// exact 32-bank permutation). W pre-packed half2 k-pairs. cp.async 3-stage.
template <int DIN, int DOUT>
__launch_bounds__(512)
__global__ void k_gemm_tc(const __half* __restrict__ A0, const __half* __restrict__ A1,
                          const uint32_t* __restrict__ W0p, const uint32_t* __restrict__ W1p,
                          const float* __restrict__ bias, const float* __restrict__ gamma,
                          const float* __restrict__ beta, __half* __restrict__ out, int n) {
    extern __shared__ float sm[];
    constexpr int NCH = DIN / 32;         // 32 k-halves per chunk
    constexpr int TOT = 2 * NCH;
    constexpr int NT = DOUT / 32;
    constexpr int APH = 40;               // A pitch in halves (80 B)
    constexpr int AHSZ = 128 * APH;       // halves per A stage
    constexpr int BPH = DOUT + 8;         // B pitch (half2 words)
    constexpr int BSZ = 16 * BPH;         // words per B stage

    __half* Ah = (__half*)sm;
    __half* Ab[3] = { Ah, Ah + AHSZ, Ah + 2 * AHSZ };
    float* after = sm + (3 * AHSZ) / 2;
    uint32_t* Bb[3] = { (uint32_t*)after, (uint32_t*)after + BSZ, (uint32_t*)after + 2 * BSZ };
    float* sp = after + 3 * BSZ;          // bias|gamma|beta
    float* sln = sp + 3 * DOUT;           // [128][4] float2

    int t = threadIdx.x;
    int wid = t >> 5, lane = t & 31;
    int g = lane >> 2, tq = lane & 3;
    int mw = wid & 3, nq = wid >> 2;
    int nbase = nq * (DOUT / 4);
    int row0 = blockIdx.x * 128;

    for (int i = t; i < DOUT; i += 512) {
        sp[i] = bias[i];
        sp[DOUT + i] = gamma[i];
        sp[2 * DOUT + i] = beta[i];
    }
    __syncthreads();

    float acc[2][NT][4];
#pragma unroll
    for (int ms = 0; ms < 2; ms++)
#pragma unroll
        for (int nt = 0; nt < NT; nt++)
#pragma unroll
            for (int j = 0; j < 4; j++) acc[ms][nt][j] = 0.f;

    auto copy_chunk = [&](int c, int ib) {
        const __half* A = (c < NCH) ? A0 : A1;
        const uint32_t* W = (c < NCH) ? W0p : W1p;
        int cc = (c < NCH) ? c : c - NCH;
        int k0 = cc * 32;        // half k base
        int kph = cc * 16;       // half2 W row base
        uint32_t abase = su32(Ab[ib]);
        uint32_t bbase = su32(Bb[ib]);
        {   // A: 128 rows x 64B = 512 cp16, one per thread
            int r = t >> 2, seg = t & 3;
            int gr = row0 + r;
            bool ok = gr < n;
            int cr = ok ? gr : (n - 1);
            cpa16(abase + (uint32_t)(r * 80 + seg * 16),
                  A + (size_t)cr * DIN + k0 + seg * 8, ok);
        }
#pragma unroll
        for (int i = 0; i < DOUT / 128; i++) { // B: 16 rows x DOUT half2
            int s = t + i * 512;
            int kr = s / (DOUT / 4), c4 = s % (DOUT / 4);
            cpa16(bbase + (uint32_t)(kr * BPH + c4 * 4) * 4,
                  W + (size_t)(kph + kr) * DOUT + c4 * 4, true);
        }
    };

    auto mma_chunk = [&](int ib) {
        const __half* As = Ab[ib];
        const uint32_t* Bs = Bb[ib];
#pragma unroll
        for (int ks = 0; ks < 2; ks++) {
            int kb = ks * 16;    // half col base
            int kpb = ks * 8;    // half2 B row base
            uint32_t bf0[NT], bf1[NT];
#pragma unroll
            for (int nt = 0; nt < NT; nt++) {
                int nn = nbase + nt * 8 + g;
                bf0[nt] = Bs[(kpb + tq) * BPH + nn];
                bf1[nt] = Bs[(kpb + tq + 4) * BPH + nn];
            }
#pragma unroll
            for (int ms = 0; ms < 2; ms++) {
                int ar = mw * 32 + ms * 16 + g;
                uint32_t a0 = *(const uint32_t*)&As[ar * APH + kb + 2 * tq];
                uint32_t a1 = *(const uint32_t*)&As[(ar + 8) * APH + kb + 2 * tq];
                uint32_t a2 = *(const uint32_t*)&As[ar * APH + kb + 2 * tq + 8];
                uint32_t a3 = *(const uint32_t*)&As[(ar + 8) * APH + kb + 2 * tq + 8];
#pragma unroll
                for (int nt = 0; nt < NT; nt++)
                    mma_f16(acc[ms][nt], a0, a1, a2, a3, bf0[nt], bf1[nt]);
            }
        }
    };

    copy_chunk(0, 0); CP_COMMIT();
    copy_chunk(1, 1); CP_COMMIT();
    for (int c = 0; c < TOT; c++) {
        if (c < TOT - 1) CP_WAIT1(); else CP_WAIT0();
        __syncthreads();
        if (c + 2 < TOT) { copy_chunk(c + 2, (c + 2) % 3); CP_COMMIT(); }
        mma_chunk(c % 3);
    }

    // ---- epilogue: +bias, LN over DOUT (4 n-quarter partials), ReLU, fp16 out ----
#pragma unroll
    for (int ms = 0; ms < 2; ms++) {
        float s0 = 0.f, ss0 = 0.f, s1 = 0.f, ss1 = 0.f;
#pragma unroll
        for (int nt = 0; nt < NT; nt++) {
            int col = nbase + nt * 8 + 2 * tq;
            float b0 = sp[col], b1 = sp[col + 1];
            acc[ms][nt][0] += b0; acc[ms][nt][1] += b1;
            acc[ms][nt][2] += b0; acc[ms][nt][3] += b1;
            s0 += acc[ms][nt][0] + acc[ms][nt][1];
            ss0 += acc[ms][nt][0] * acc[ms][nt][0] + acc[ms][nt][1] * acc[ms][nt][1];
            s1 += acc[ms][nt][2] + acc[ms][nt][3];
            ss1 += acc[ms][nt][2] * acc[ms][nt][2] + acc[ms][nt][3] * acc[ms][nt][3];
        }
#pragma unroll
        for (int o = 1; o <= 2; o <<= 1) {
            s0 += __shfl_xor_sync(0xffffffffu, s0, o);
            ss0 += __shfl_xor_sync(0xffffffffu, ss0, o);
            s1 += __shfl_xor_sync(0xffffffffu, s1, o);
            ss1 += __shfl_xor_sync(0xffffffffu, ss1, o);
        }
        if (tq == 0) {
            int r0 = mw * 32 + ms * 16 + g;
            ((float2*)sln)[r0 * 4 + nq] = make_float2(s0, ss0);
            ((float2*)sln)[(r0 + 8) * 4 + nq] = make_float2(s1, ss1);
        }
    }
    __syncthreads();
#pragma unroll
    for (int ms = 0; ms < 2; ms++) {
        int rl0 = mw * 32 + ms * 16 + g, rl1 = rl0 + 8;
        float s0 = 0.f, ss0 = 0.f, s1 = 0.f, ss1 = 0.f;
#pragma unroll
        for (int q = 0; q < 4; q++) {
            float2 p0 = ((float2*)sln)[rl0 * 4 + q];
            float2 p1 = ((float2*)sln)[rl1 * 4 + q];
            s0 += p0.x; ss0 += p0.y;
            s1 += p1.x; ss1 += p1.y;
        }
        float mu0 = s0 * (1.0f / DOUT);
        float rs0 = rsqrtf(ss0 * (1.0f / DOUT) - mu0 * mu0 + 1e-5f);
        float mu1 = s1 * (1.0f / DOUT);
        float rs1 = rsqrtf(ss1 * (1.0f / DOUT) - mu1 * mu1 + 1e-5f);
        int grow0 = row0 + rl0, grow1 = row0 + rl1;
#pragma unroll
        for (int nt = 0; nt < NT; nt++) {
            int col = nbase + nt * 8 + 2 * tq;
            float ga0 = sp[DOUT + col], ga1 = sp[DOUT + col + 1];
            float bt0 = sp[2 * DOUT + col], bt1 = sp[2 * DOUT + col + 1];
            if (grow0 < n) {
                float vx = fmaxf((acc[ms][nt][0] - mu0) * rs0 * ga0 + bt0, 0.f);
                float vy = fmaxf((acc[ms][nt][1] - mu0) * rs0 * ga1 + bt1, 0.f);
                *(__half2*)(out + (size_t)grow0 * DOUT + col) = __floats2half2_rn(vx, vy);
            }
            if (grow1 < n) {
                float vx = fmaxf((acc[ms][nt][2] - mu1) * rs1 * ga0 + bt0, 0.f);
                float vy = fmaxf((acc[ms][nt][3] - mu1) * rs1 * ga1 + bt1, 0.f);
                *(__half2*)(out + (size_t)grow1 * DOUT + col) = __floats2half2_rn(vx, vy);
            }
        }
    }
}

// ================= dual-output GEMM: YM = X@W0, YR = X@W1 + b (fp16 out) =================
template <int DIN, int DOUT>
__launch_bounds__(512)
__global__ void k_gemm_dual(const __half* __restrict__ X,
                            const uint32_t* __restrict__ W0p, const uint32_t* __restrict__ W1p,
                            const float* __restrict__ bias,
                            __half* __restrict__ ym, __half* __restrict__ yr, int n) {
    extern __shared__ float sm[];
    constexpr int NCH = DIN / 32;
    constexpr int NT = DOUT / 32;
    constexpr int APH = 40;
    constexpr int AHSZ = 128 * APH;
    constexpr int BPH = DOUT + 8;
    constexpr int BSZ = 16 * BPH;

    __half* Ah = (__half*)sm;
    __half* Ab[3] = { Ah, Ah + AHSZ, Ah + 2 * AHSZ };
    float* after = sm + (3 * AHSZ) / 2;
    uint32_t* B0b[3] = { (uint32_t*)after, (uint32_t*)after + BSZ, (uint32_t*)after + 2 * BSZ };
    uint32_t* B1b[3] = { (uint32_t*)after + 3 * BSZ, (uint32_t*)after + 4 * BSZ, (uint32_t*)after + 5 * BSZ };
    float* sp = after + 6 * BSZ;

    int t = threadIdx.x;
    int wid = t >> 5, lane = t & 31;
    int g = lane >> 2, tq = lane & 3;
    int mw = wid & 3, nq = wid >> 2;
    int nbase = nq * (DOUT / 4);
    int row0 = blockIdx.x * 128;

    for (int i = t; i < DOUT; i += 512) sp[i] = bias[i];
    __syncthreads();

    float accM[2][NT][4], accR[2][NT][4];
#pragma unroll
    for (int ms = 0; ms < 2; ms++)
#pragma unroll
        for (int nt = 0; nt < NT; nt++)
#pragma unroll
            for (int j = 0; j < 4; j++) { accM[ms][nt][j] = 0.f; accR[ms][nt][j] = 0.f; }

    auto copy_chunk = [&](int c, int ib) {
        int k0 = c * 32;
        int kph = c * 16;
        uint32_t abase = su32(Ab[ib]);
        uint32_t b0base = su32(B0b[ib]);
        uint32_t b1base = su32(B1b[ib]);
        {
            int r = t >> 2, seg = t & 3;
            int gr = row0 + r;
            bool ok = gr < n;
            int cr = ok ? gr : (n - 1);
            cpa16(abase + (uint32_t)(r * 80 + seg * 16),
                  X + (size_t)cr * DIN + k0 + seg * 8, ok);
        }
        {
            int kr = t / (DOUT / 4), c4 = t % (DOUT / 4);
            size_t wo = (size_t)(kph + kr) * DOUT + c4 * 4;
            uint32_t so = (uint32_t)(kr * BPH + c4 * 4) * 4;
            cpa16(b0base + so, W0p + wo, true);
            cpa16(b1base + so, W1p + wo, true);
        }
    };

    auto mma_chunk = [&](int ib) {
        const __half* As = Ab[ib];
        const uint32_t* B0s = B0b[ib];
        const uint32_t* B1s = B1b[ib];
#pragma unroll
        for (int ks = 0; ks < 2; ks++) {
            int kb = ks * 16;
            int kpb = ks * 8;
            uint32_t bfM0[NT], bfM1[NT], bfR0[NT], bfR1[NT];
#pragma unroll
            for (int nt = 0; nt < NT; nt++) {
                int nn = nbase + nt * 8 + g;
                bfM0[nt] = B0s[(kpb + tq) * BPH + nn];
                bfM1[nt] = B0s[(kpb + tq + 4) * BPH + nn];
                bfR0[nt] = B1s[(kpb + tq) * BPH + nn];
                bfR1[nt] = B1s[(kpb + tq + 4) * BPH + nn];
            }
#pragma unroll
            for (int ms = 0; ms < 2; ms++) {
                int ar = mw * 32 + ms * 16 + g;
                uint32_t a0 = *(const uint32_t*)&As[ar * APH + kb + 2 * tq];
                uint32_t a1 = *(const uint32_t*)&As[(ar + 8) * APH + kb + 2 * tq];
                uint32_t a2 = *(const uint32_t*)&As[ar * APH + kb + 2 * tq + 8];
                uint32_t a3 = *(const uint32_t*)&As[(ar + 8) * APH + kb + 2 * tq + 8];
#pragma unroll
                for (int nt = 0; nt < NT; nt++) {
                    mma_f16(accM[ms][nt], a0, a1, a2, a3, bfM0[nt], bfM1[nt]);
                    mma_f16(accR[ms][nt], a0, a1, a2, a3, bfR0[nt], bfR1[nt]);
                }
            }
        }
    };

    copy_chunk(0, 0); CP_COMMIT();
    copy_chunk(1, 1); CP_COMMIT();
    for (int c = 0; c < NCH; c++) {
        if (c < NCH - 1) CP_WAIT1(); else CP_WAIT0();
        __syncthreads();
        if (c + 2 < NCH) { copy_chunk(c + 2, (c + 2) % 3); CP_COMMIT(); }
        mma_chunk(c % 3);
    }

#pragma unroll
    for (int ms = 0; ms < 2; ms++) {
        int rl0 = mw * 32 + ms * 16 + g, rl1 = rl0 + 8;
        int grow0 = row0 + rl0, grow1 = row0 + rl1;
#pragma unroll
        for (int nt = 0; nt < NT; nt++) {
            int col = nbase + nt * 8 + 2 * tq;
            float b0 = sp[col], b1 = sp[col + 1];
            if (grow0 < n) {
                *(__half2*)(ym + (size_t)grow0 * DOUT + col) = __floats2half2_rn(accM[ms][nt][0], accM[ms][nt][1]);
                *(__half2*)(yr + (size_t)grow0 * DOUT + col) = __floats2half2_rn(accR[ms][nt][0] + b0, accR[ms][nt][1] + b1);
            }
            if (grow1 < n) {
                *(__half2*)(ym + (size_t)grow1 * DOUT + col) = __floats2half2_rn(accM[ms][nt][2], accM[ms][nt][3]);
                *(__half2*)(yr + (size_t)grow1 * DOUT + col) = __floats2half2_rn(accR[ms][nt][2] + b0, accR[ms][nt][3] + b1);
            }
        }
    }
}

// ================= elementwise: out = ReLU(LN(mean + yr)), D=128, warp/row, fp16 =================
__global__ void k_addlnrelu(const __half* __restrict__ meanp, const __half* __restrict__ yr,
                            const float* __restrict__ gamma, const float* __restrict__ beta,
                            __half* __restrict__ out, int n) {
    int row = (blockIdx.x * blockDim.x + threadIdx.x) >> 5;
    int lane = threadIdx.x & 31;
    if (row >= n) return;
    uint2 mu2 = ((const uint2*)(meanp + (size_t)row * 128))[lane];
    uint2 yu2 = ((const uint2*)(yr + (size_t)row * 128))[lane];
    float2 m0 = __half22float2(*(__half2*)&mu2.x), m1 = __half22float2(*(__half2*)&mu2.y);
    float2 y0 = __half22float2(*(__half2*)&yu2.x), y1 = __half22float2(*(__half2*)&yu2.y);
    float v[4] = { m0.x + y0.x, m0.y + y0.y, m1.x + y1.x, m1.y + y1.y };
    float s = v[0] + v[1] + v[2] + v[3];
    float ss = v[0] * v[0] + v[1] * v[1] + v[2] * v[2] + v[3] * v[3];
#pragma unroll
    for (int o = 16; o; o >>= 1) {
        s += __shfl_xor_sync(0xffffffffu, s, o);
        ss += __shfl_xor_sync(0xffffffffu, ss, o);
    }
    float mu = s * (1.0f / 128.0f);
    float var = ss * (1.0f / 128.0f) - mu * mu;
    float rs = rsqrtf(var + 1e-5f);
    float4 g4 = ((const float4*)gamma)[lane];
    float4 b4 = ((const float4*)beta)[lane];
    float o0 = fmaxf((v[0] - mu) * rs * g4.x + b4.x, 0.f);
    float o1 = fmaxf((v[1] - mu) * rs * g4.y + b4.y, 0.f);
    float o2 = fmaxf((v[2] - mu) * rs * g4.z + b4.z, 0.f);
    float o3 = fmaxf((v[3] - mu) * rs * g4.w + b4.w, 0.f);
    __half2 h0 = __floats2half2_rn(o0, o1);
    __half2 h1 = __floats2half2_rn(o2, o3);
    ((uint2*)(out + (size_t)row * 128))[lane] = make_uint2(*(uint32_t*)&h0, *(uint32_t*)&h1);
}

// ================= final layer part 1: ym9 = x@Wm4, yr9 = x@Wr4 + b4 =================
__global__ void k_out_dual(const __half* __restrict__ x,
                           const float* __restrict__ wm, const float* __restrict__ wr,
                           const float* __restrict__ bias,
                           float* __restrict__ ym9, float* __restrict__ yr9, int n) {
    __shared__ float swm[128 * 9];
    __shared__ float swr[128 * 9];
    __shared__ float sb[9];
    for (int i = threadIdx.x; i < 128 * 9; i += blockDim.x) {
        swm[i] = wm[i];
        swr[i] = wr[i];
    }
    if (threadIdx.x < 9) sb[threadIdx.x] = bias[threadIdx.x];
    __syncthreads();

    int gw = (blockIdx.x * blockDim.x + threadIdx.x) >> 5;
    int lane = threadIdx.x & 31;
    if (gw >= n) return;

    uint2 u = ((const uint2*)(x + (size_t)gw * 128))[lane];
    float2 f0 = __half22float2(*(__half2*)&u.x);
    float2 f1 = __half22float2(*(__half2*)&u.y);
    float x4[4] = { f0.x, f0.y, f1.x, f1.y };

    float om[9], orr[9];
#pragma unroll
    for (int j = 0; j < 9; j++) { om[j] = 0.f; orr[j] = 0.f; }
#pragma unroll
    for (int q = 0; q < 4; q++) {
        int k = lane * 4 + q;
#pragma unroll
        for (int j = 0; j < 9; j++) {
            om[j] += x4[q] * swm[k * 9 + j];
            orr[j] += x4[q] * swr[k * 9 + j];
        }
    }
#pragma unroll
    for (int j = 0; j < 9; j++)
#pragma unroll
        for (int s = 16; s; s >>= 1) {
            om[j] += __shfl_xor_sync(0xffffffffu, om[j], s);
            orr[j] += __shfl_xor_sync(0xffffffffu, orr[j], s);
        }
    if (lane < 9) {
        ym9[(size_t)gw * 9 + lane] = om[lane];
        yr9[(size_t)gw * 9 + lane] = orr[lane] + sb[lane];
    }
}

// ================= final layer part 2: out = mean(ym9[src]) + yr9; re-zero g_deg =================
__global__ void k_agg9(const float* __restrict__ ym9, const float* __restrict__ yr9,
                       float* __restrict__ out, int n) {
    int gt = blockIdx.x * blockDim.x + threadIdx.x;
    if (gt < NMAX) g_deg[gt] = 0;
    int gw = gt >> 5;
    int lane = threadIdx.x & 31;
    if (gw >= n) return;
    int b = g_off[gw], e = g_off[gw + 1];
    float acc[9];
#pragma unroll
    for (int j = 0; j < 9; j++) acc[j] = 0.f;
    for (int j = b + lane; j < e; j += 32) {
        const float* row = ym9 + (size_t)g_csr[j] * 9;
#pragma unroll
        for (int c = 0; c < 9; c++) acc[c] += row[c];
    }
#pragma unroll
    for (int c = 0; c < 9; c++)
#pragma unroll
        for (int s = 16; s; s >>= 1) acc[c] += __shfl_xor_sync(0xffffffffu, acc[c], s);
    if (lane < 9) {
        float inv = 1.0f / g_cnt[gw];
        out[(size_t)gw * 9 + lane] = acc[lane] * inv + yr9[(size_t)gw * 9 + lane];
    }
}

// ================= launch =================
extern "C" void kernel_launch(void* const* d_in, const int* in_sizes, int n_in,
                              void* d_out, int out_size) {
    const float* z = (const float*)d_in[0];
    const int* ei = (const int*)d_in[1];
    const float* wm1 = (const float*)d_in[2];
    const float* wr1 = (const float*)d_in[3];
    const float* b1 = (const float*)d_in[4];
    const float* g1 = (const float*)d_in[5];
    const float* be1 = (const float*)d_in[6];
    const float* wm2 = (const float*)d_in[7];
    const float* wr2 = (const float*)d_in[8];
    const float* b2 = (const float*)d_in[9];
    const float* g2 = (const float*)d_in[10];
    const float* be2 = (const float*)d_in[11];
    const float* wm3 = (const float*)d_in[12];
    const float* wr3 = (const float*)d_in[13];
    const float* b3 = (const float*)d_in[14];
    const float* g3 = (const float*)d_in[15];
    const float* be3 = (const float*)d_in[16];
    const float* wm4 = (const float*)d_in[17];
    const float* wr4 = (const float*)d_in[18];
    const float* b4 = (const float*)d_in[19];

    int N = in_sizes[0] / 128;
    int E = in_sizes[1] / 2;
    const int* src = ei;
    const int* dst = ei + E;

    __half *hz, *hA, *hB, *hM;
    float *ym9, *yr9;
    uint32_t *w1m, *w1r, *w2m, *w2r, *w3m, *w3r;
    void* p;
    cudaGetSymbolAddress(&p, g_hz);  hz = (__half*)p;
    cudaGetSymbolAddress(&p, g_hA);  hA = (__half*)p;
    cudaGetSymbolAddress(&p, g_hB);  hB = (__half*)p;
    cudaGetSymbolAddress(&p, g_hM);  hM = (__half*)p;
    cudaGetSymbolAddress(&p, g_ym9); ym9 = (float*)p;
    cudaGetSymbolAddress(&p, g_yr9); yr9 = (float*)p;
    cudaGetSymbolAddress(&p, g_w1m); w1m = (uint32_t*)p;
    cudaGetSymbolAddress(&p, g_w1r); w1r = (uint32_t*)p;
    cudaGetSymbolAddress(&p, g_w2m); w2m = (uint32_t*)p;
    cudaGetSymbolAddress(&p, g_w2r); w2r = (uint32_t*)p;
    cudaGetSymbolAddress(&p, g_w3m); w3m = (uint32_t*)p;
    cudaGetSymbolAddress(&p, g_w3r); w3r = (uint32_t*)p;

    // smem bytes: A: 3*128*40 halves = 7680 words; B: 3*16*(DOUT+8) words (x2 arrays for dual)
    const int SM256 = (7680 + 3 * 16 * 264 + 3 * 256 + 1024) * 4;
    const int SMD128 = (7680 + 6 * 16 * 136 + 128) * 4;
    cudaFuncSetAttribute(k_gemm_tc<128, 256>, cudaFuncAttributeMaxDynamicSharedMemorySize, SM256);
    cudaFuncSetAttribute(k_gemm_tc<256, 256>, cudaFuncAttributeMaxDynamicSharedMemorySize, SM256);
    cudaFuncSetAttribute(k_gemm_dual<256, 128>, cudaFuncAttributeMaxDynamicSharedMemorySize, SMD128);

    // CSR build
    k_hist<<<(E + 255) / 256, 256>>>(dst, E);
    k_scan<<<1, 1024>>>(N);
    k_scatter<<<(E + 255) / 256, 256>>>(src, dst, E);

    int aggBlocks = (N + 7) / 8;
    int gemmBlocks = (N + 127) / 128;

    // z -> fp16
    k_z2h<<<(N * 64 + 255) / 256, 256>>>(z, hz, N * 64);
    // Layer 1 agg (mean of z, fp16)
    k_aggh<128><<<aggBlocks, 256>>>(hz, hM, N);

    // weight pack (half2 k-pairs)
    k_packh2<<<(64 * 256 + 255) / 256, 256>>>(wm1, w1m, 64, 256);
    k_packh2<<<(64 * 256 + 255) / 256, 256>>>(wr1, w1r, 64, 256);
    k_packh2<<<(128 * 256 + 255) / 256, 256>>>(wm2, w2m, 128, 256);
    k_packh2<<<(128 * 256 + 255) / 256, 256>>>(wr2, w2r, 128, 256);
    k_packh2<<<(128 * 128 + 255) / 256, 256>>>(wm3, w3m, 128, 128);
    k_packh2<<<(128 * 128 + 255) / 256, 256>>>(wr3, w3r, 128, 128);

    // Layer 1: 128 -> 256 (aggregate-first)
    k_gemm_tc<128, 256><<<gemmBlocks, 512, SM256>>>(hM, hz, w1m, w1r, b1, g1, be1, hA, N);
    // Layer 2: 256 -> 256 (aggregate-first)
    k_aggh<256><<<aggBlocks, 256>>>(hA, hM, N);
    k_gemm_tc<256, 256><<<gemmBlocks, 512, SM256>>>(hM, hA, w2m, w2r, b2, g2, be2, hB, N);
    // Layer 3: 256 -> 128 (aggregate-AFTER): ym->hM, yr->hA
    k_gemm_dual<256, 128><<<gemmBlocks, 512, SMD128>>>(hB, w3m, w3r, b3, hM, hA, N);
    k_aggh<128><<<aggBlocks, 256>>>(hM, hB, N);                  // mean(ym) -> hB
    k_addlnrelu<<<aggBlocks, 256>>>(hB, hA, g3, be3, hM, N);     // x3 -> hM
    // Layer 4: 128 -> 9 (aggregate-AFTER)
    k_out_dual<<<aggBlocks, 256>>>(hM, wm4, wr4, b4, ym9, yr9, N);
    k_agg9<<<aggBlocks, 256>>>(ym9, yr9, (float*)d_out, N);
}